// round 14
// baseline (speedup 1.0000x reference)
#include <cuda_runtime.h>
#include <cuda_bf16.h>
#include <math.h>
#include <stdint.h>

typedef __nv_bfloat16 bf16;

#define C_DIM   1024
#define T_DIM   1024
#define B_DIM   4
#define H_DIM   16
#define DK      64
#define DFF_DIM 4096
#define M_ROWS  4096

// Q pre-scale: 1/sqrt(dk) * log2(e)  (softmax via exp2)
#define QSCALE 0.1803368801111244f

// ---------------- scratch (device globals; no allocation allowed) ----------
__device__ float g_o [M_ROWS * C_DIM];
__device__ float g_y [M_ROWS * C_DIM];
__device__ float g_y2[M_ROWS * C_DIM];

__device__ bf16 g_qh [M_ROWS * C_DIM], g_ql [M_ROWS * C_DIM];
__device__ bf16 g_kh [M_ROWS * C_DIM], g_kl [M_ROWS * C_DIM];
__device__ bf16 g_vh [M_ROWS * C_DIM], g_vl [M_ROWS * C_DIM];
__device__ bf16 g_dsth[M_ROWS * C_DIM], g_dstl[M_ROWS * C_DIM];
__device__ bf16 g_srch[M_ROWS * C_DIM], g_srcl[M_ROWS * C_DIM];
__device__ bf16 g_yh  [M_ROWS * C_DIM], g_yl  [M_ROWS * C_DIM];
__device__ bf16 g_y2h [M_ROWS * C_DIM], g_y2l [M_ROWS * C_DIM];
__device__ bf16 g_ath [M_ROWS * C_DIM], g_atl [M_ROWS * C_DIM];
__device__ bf16 g_ffh [M_ROWS * DFF_DIM], g_ffl[M_ROWS * DFF_DIM];
__device__ bf16 g_wth [16 * 1024 * 1024], g_wtl[16 * 1024 * 1024];

// ---------------- PTX helpers (plain sm_103: no tcgen05/TMEM) --------------
__device__ __forceinline__ uint32_t smem_u32(const void* p) {
    uint32_t a;
    asm("{ .reg .u64 t; cvta.to.shared.u64 t, %1; cvt.u32.u64 %0, t; }" : "=r"(a) : "l"(p));
    return a;
}
#define SMEM_SWIZZLE_128B(o) ((o) ^ (((o) >> 3) & 0x70))

#define CP16(dst, src) \
    asm volatile("cp.async.cg.shared.global [%0], [%1], 16;" :: "r"(dst), "l"(src) : "memory")
#define CP_COMMIT() asm volatile("cp.async.commit_group;" ::: "memory")
#define CP_WAIT(n)  asm volatile("cp.async.wait_group %0;" :: "n"(n) : "memory")

#define LDSM4(r0, r1, r2, r3, a) \
    asm volatile("ldmatrix.sync.aligned.m8n8.x4.shared.b16 {%0,%1,%2,%3}, [%4];" \
                 : "=r"(r0), "=r"(r1), "=r"(r2), "=r"(r3) : "r"(a))
#define LDSM4T(r0, r1, r2, r3, a) \
    asm volatile("ldmatrix.sync.aligned.m8n8.x4.trans.shared.b16 {%0,%1,%2,%3}, [%4];" \
                 : "=r"(r0), "=r"(r1), "=r"(r2), "=r"(r3) : "r"(a))

#define MMA16816(d, a, b0, b1) \
    asm volatile("mma.sync.aligned.m16n8k16.row.col.f32.bf16.bf16.f32 " \
                 "{%0,%1,%2,%3}, {%4,%5,%6,%7}, {%8,%9}, {%0,%1,%2,%3};" \
                 : "+f"((d)[0]), "+f"((d)[1]), "+f"((d)[2]), "+f"((d)[3]) \
                 : "r"((a)[0]), "r"((a)[1]), "r"((a)[2]), "r"((a)[3]), "r"(b0), "r"(b1))

__device__ __forceinline__ void split2(float v, bf16& h, bf16& l) {
    h = __float2bfloat16(v);
    l = __float2bfloat16(v - __bfloat162float(h));
}
__device__ __forceinline__ void split_pack(float x, float y, uint32_t& hp, uint32_t& lp) {
    bf16 hx, lx, hy, ly;
    split2(x, hx, lx);
    split2(y, hy, ly);
    __nv_bfloat162 h2(hx, hy), l2(lx, ly);
    hp = *(uint32_t*)&h2;
    lp = *(uint32_t*)&l2;
}

// ---------------- HMMA GEMM (R8 config; RAW-chain-free MMA order) ----------
// CTA 128x128, BK=32, 8 warps (2x4), warp tile 64x32, 2 CTAs/SM.
// Stage 32KB (4 regions x 8KB, 64B rows), double-buffered.
// Swizzle: chunk' = chunk ^ ((row>>1)&3).
// MMAs issued in three 16-independent-accumulator passes (hi*bh, lo*bh, hi*bl)
// so no accumulator receives back-to-back dependent MMAs.
#define GSTAGE 32768

__global__ __launch_bounds__(256, 2) void gemm_hmma(
    const bf16* __restrict__ Ah, const bf16* __restrict__ Al,
    const bf16* __restrict__ Bh, const bf16* __restrict__ Bl,
    const float* __restrict__ bias,
    float* __restrict__ outF, bf16* __restrict__ outH, bf16* __restrict__ outL,
    int M, int N, int K, int do_gelu, float oscale)
{
    extern __shared__ char dynsm[];
    const uint32_t sb0 = (smem_u32(dynsm) + 1023) & ~1023u;

    const int tid = threadIdx.x;
    const int m0 = blockIdx.y * 128;
    const int n0 = blockIdx.x * 128;
    const int w = tid >> 5, lane = tid & 31;
    const int wm0 = (w >> 2) * 64;
    const int wn0 = (w & 3) * 32;

    const int lr = tid >> 1;
    const int lc = (tid & 1) * 2;

    const int arow = lane & 15;
    const int ahalf = lane >> 4;
    const int brow = ((lane >> 4) & 1) * 8 + (lane & 7);
    const int bhalf = (lane >> 3) & 1;

    float acc[4][4][4];
#pragma unroll
    for (int i = 0; i < 4; i++)
#pragma unroll
        for (int j = 0; j < 4; j++)
#pragma unroll
            for (int r = 0; r < 4; r++) acc[i][j][r] = 0.f;

    const int NC = K >> 5;

    auto load_stage = [&](uint32_t sb, int k0) {
        const bf16* pa_h = Ah + (size_t)(m0 + lr) * K + k0 + lc * 8;
        const bf16* pa_l = Al + (size_t)(m0 + lr) * K + k0 + lc * 8;
        const bf16* pb_h = Bh + (size_t)(n0 + lr) * K + k0 + lc * 8;
        const bf16* pb_l = Bl + (size_t)(n0 + lr) * K + k0 + lc * 8;
        const uint32_t sw = (uint32_t)((lr >> 1) & 3);
#pragma unroll
        for (int j = 0; j < 2; j++) {
            const uint32_t off = (uint32_t)(lr * 64) + ((((uint32_t)(lc + j)) ^ sw) << 4);
            CP16(sb + off,         pa_h + j * 8);
            CP16(sb + 8192  + off, pa_l + j * 8);
            CP16(sb + 16384 + off, pb_h + j * 8);
            CP16(sb + 24576 + off, pb_l + j * 8);
        }
    };

    load_stage(sb0, 0);
    CP_COMMIT();

    for (int c = 0; c < NC; c++) {
        if (c + 1 < NC) {
            load_stage(sb0 + ((c + 1) & 1) * GSTAGE, (c + 1) * 32);
            CP_COMMIT();
            CP_WAIT(1);
        } else {
            CP_WAIT(0);
        }
        __syncthreads();

        const uint32_t sb = sb0 + (c & 1) * GSTAGE;
        const uint32_t sAh = sb, sAl = sb + 8192, sBh = sb + 16384, sBl = sb + 24576;

#pragma unroll
        for (int ks = 0; ks < 2; ks++) {
            uint32_t ah[4][4], al[4][4];
#pragma unroll
            for (int mt = 0; mt < 4; mt++) {
                const int row = wm0 + mt * 16 + arow;
                const uint32_t chunk = (uint32_t)(ks * 2 + ahalf);
                const uint32_t ad = (uint32_t)(row * 64) +
                                    ((chunk ^ ((uint32_t)(row >> 1) & 3)) << 4);
                LDSM4(ah[mt][0], ah[mt][1], ah[mt][2], ah[mt][3], sAh + ad);
                LDSM4(al[mt][0], al[mt][1], al[mt][2], al[mt][3], sAl + ad);
            }
            uint32_t fb[4][2];
            uint32_t bd0, bd1;
            {
                const int r0 = wn0 + brow, r1 = wn0 + 16 + brow;
                const uint32_t chunk = (uint32_t)(ks * 2 + bhalf);
                bd0 = (uint32_t)(r0 * 64) + ((chunk ^ ((uint32_t)(r0 >> 1) & 3)) << 4);
                bd1 = (uint32_t)(r1 * 64) + ((chunk ^ ((uint32_t)(r1 >> 1) & 3)) << 4);
            }
            LDSM4(fb[0][0], fb[0][1], fb[1][0], fb[1][1], sBh + bd0);
            LDSM4(fb[2][0], fb[2][1], fb[3][0], fb[3][1], sBh + bd1);
            // pass 1: ah * Bh  (16 independent accumulators)
#pragma unroll
            for (int mt = 0; mt < 4; mt++)
#pragma unroll
                for (int nt = 0; nt < 4; nt++)
                    MMA16816(acc[mt][nt], ah[mt], fb[nt][0], fb[nt][1]);
            // pass 2: al * Bh  (revisits each acc only after 15 others)
#pragma unroll
            for (int mt = 0; mt < 4; mt++)
#pragma unroll
                for (int nt = 0; nt < 4; nt++)
                    MMA16816(acc[mt][nt], al[mt], fb[nt][0], fb[nt][1]);
            // reuse fb registers for B-lo
            LDSM4(fb[0][0], fb[0][1], fb[1][0], fb[1][1], sBl + bd0);
            LDSM4(fb[2][0], fb[2][1], fb[3][0], fb[3][1], sBl + bd1);
            // pass 3: ah * Bl
#pragma unroll
            for (int mt = 0; mt < 4; mt++)
#pragma unroll
                for (int nt = 0; nt < 4; nt++)
                    MMA16816(acc[mt][nt], ah[mt], fb[nt][0], fb[nt][1]);
        }
        __syncthreads();
    }

    const int g = lane >> 2, q = lane & 3;
#pragma unroll
    for (int mt = 0; mt < 4; mt++) {
#pragma unroll
        for (int half = 0; half < 2; half++) {
            const int row = m0 + wm0 + mt * 16 + half * 8 + g;
#pragma unroll
            for (int nt = 0; nt < 4; nt++) {
                const int col = n0 + wn0 + nt * 8 + q * 2;
                float v0 = acc[mt][nt][half * 2 + 0] + __ldg(bias + col);
                float v1 = acc[mt][nt][half * 2 + 1] + __ldg(bias + col + 1);
                if (do_gelu) {
                    v0 = 0.5f * v0 * (1.f + erff(v0 * 0.70710678118654752f));
                    v1 = 0.5f * v1 * (1.f + erff(v1 * 0.70710678118654752f));
                }
                const size_t idx = (size_t)row * N + col;
                if (outF) *(float2*)(outF + idx) = make_float2(v0, v1);
                if (outH) {
                    uint32_t hp, lp;
                    split_pack(v0 * oscale, v1 * oscale, hp, lp);
                    *(uint32_t*)(outH + idx) = hp;
                    *(uint32_t*)(outL + idx) = lp;
                }
            }
        }
    }
}

// ---------------- HMMA flash attention (RAW-chain-free MMA order) -----------
__global__ __launch_bounds__(256) void attention_hmma(
    const bf16* __restrict__ Qh, const bf16* __restrict__ Ql,
    const bf16* __restrict__ Kh, const bf16* __restrict__ Kl,
    const bf16* __restrict__ Vh, const bf16* __restrict__ Vl,
    bf16* __restrict__ OH, bf16* __restrict__ OL,
    int causal)
{
    extern __shared__ char dynsm[];
    const uint32_t sQ  = (smem_u32(dynsm) + 1023) & ~1023u;
    const uint32_t sKV = sQ + 32768;

    const int tid = threadIdx.x;
    const int w = tid >> 5, lane = tid & 31;
    const int b = blockIdx.z, h = blockIdx.y;
    const int q0 = blockIdx.x * 128;
    const int wm0 = w * 16;
    const int g = lane >> 2, qd = lane & 3;

    {
        const int r = tid >> 1, c0 = (tid & 1) * 4;
        const size_t qrow = (size_t)(b * T_DIM + q0 + r) * C_DIM + h * DK;
#pragma unroll
        for (int c = c0; c < c0 + 4; c++) {
            const uint32_t off = SMEM_SWIZZLE_128B((uint32_t)(r * 128 + c * 16));
            CP16(sQ + off,         Qh + qrow + c * 8);
            CP16(sQ + 16384 + off, Ql + qrow + c * 8);
        }
    }
    auto load_kv = [&](uint32_t sb, int k0) {
        const int r = tid >> 2, c0 = (tid & 3) * 2;
        const size_t krow = (size_t)(b * T_DIM + k0 + r) * C_DIM + h * DK;
#pragma unroll
        for (int c = c0; c < c0 + 2; c++) {
            const uint32_t off = SMEM_SWIZZLE_128B((uint32_t)(r * 128 + c * 16));
            CP16(sb + off,         Kh + krow + c * 8);
            CP16(sb + 8192  + off, Kl + krow + c * 8);
            CP16(sb + 16384 + off, Vh + krow + c * 8);
            CP16(sb + 24576 + off, Vl + krow + c * 8);
        }
    };
    load_kv(sKV, 0);
    CP_COMMIT();

    const int ntiles = causal ? (q0 + 128) / 64 : (T_DIM / 64);

    float m0 = -1e30f, m1 = -1e30f, l0 = 0.f, l1 = 0.f;
    float o[8][4];
#pragma unroll
    for (int i = 0; i < 8; i++)
#pragma unroll
        for (int j = 0; j < 4; j++) o[i][j] = 0.f;

    uint32_t fqh[4][4], fql[4][4];
    const int arow = lane & 15, ahalf = lane >> 4;
    const int brow = ((lane >> 4) & 1) * 8 + (lane & 7), bhalf = (lane >> 3) & 1;
    const int vkrow = ((lane >> 3) & 1) * 8 + (lane & 7);
    const int vdsel = lane >> 4;

    for (int it = 0; it < ntiles; it++) {
        if (it + 1 < ntiles) {
            load_kv(sKV + ((it + 1) & 1) * 32768, (it + 1) * 64);
            CP_COMMIT();
            CP_WAIT(1);
        } else {
            CP_WAIT(0);
        }
        __syncthreads();

        if (it == 0) {
#pragma unroll
            for (int ks = 0; ks < 4; ks++) {
                const int row = wm0 + arow;
                const uint32_t ad = (uint32_t)(row * 128) +
                    (((uint32_t)(ks * 32 + ahalf * 16)) ^ ((uint32_t)(row & 7) << 4));
                LDSM4(fqh[ks][0], fqh[ks][1], fqh[ks][2], fqh[ks][3], sQ + ad);
                LDSM4(fql[ks][0], fql[ks][1], fql[ks][2], fql[ks][3], sQ + 16384 + ad);
            }
        }

        const uint32_t sb = sKV + (it & 1) * 32768;

        float s[8][4];
#pragma unroll
        for (int i = 0; i < 8; i++)
#pragma unroll
            for (int j = 0; j < 4; j++) s[i][j] = 0.f;

        uint32_t fb[8][2];
#pragma unroll
        for (int ks = 0; ks < 4; ks++) {
#pragma unroll
            for (int ng = 0; ng < 4; ng++) {
                const int row = ng * 16 + brow;
                const uint32_t bd = (uint32_t)(row * 128) +
                    (((uint32_t)(ks * 32 + bhalf * 16)) ^ ((uint32_t)(row & 7) << 4));
                LDSM4(fb[2*ng][0], fb[2*ng][1], fb[2*ng+1][0], fb[2*ng+1][1], sb + bd);
            }
            // pass 1: qh * Kh  (8 independent accumulators)
#pragma unroll
            for (int nt = 0; nt < 8; nt++)
                MMA16816(s[nt], fqh[ks], fb[nt][0], fb[nt][1]);
            // pass 2: ql * Kh
#pragma unroll
            for (int nt = 0; nt < 8; nt++)
                MMA16816(s[nt], fql[ks], fb[nt][0], fb[nt][1]);
#pragma unroll
            for (int ng = 0; ng < 4; ng++) {
                const int row = ng * 16 + brow;
                const uint32_t bd = (uint32_t)(row * 128) +
                    (((uint32_t)(ks * 32 + bhalf * 16)) ^ ((uint32_t)(row & 7) << 4));
                LDSM4(fb[2*ng][0], fb[2*ng][1], fb[2*ng+1][0], fb[2*ng+1][1], sb + 8192 + bd);
            }
            // pass 3: qh * Kl
#pragma unroll
            for (int nt = 0; nt < 8; nt++)
                MMA16816(s[nt], fqh[ks], fb[nt][0], fb[nt][1]);
        }

        const int kbase = it * 64;
        const int row0 = q0 + wm0 + g, row1 = row0 + 8;
        if (causal && kbase + 63 > row0) {
#pragma unroll
            for (int nt = 0; nt < 8; nt++) {
                const int cb = kbase + nt * 8 + qd * 2;
                if (cb     > row0) s[nt][0] = -1e30f;
                if (cb + 1 > row0) s[nt][1] = -1e30f;
                if (cb     > row1) s[nt][2] = -1e30f;
                if (cb + 1 > row1) s[nt][3] = -1e30f;
            }
        }

        float mx0 = -1e30f, mx1 = -1e30f;
#pragma unroll
        for (int nt = 0; nt < 8; nt++) {
            mx0 = fmaxf(mx0, fmaxf(s[nt][0], s[nt][1]));
            mx1 = fmaxf(mx1, fmaxf(s[nt][2], s[nt][3]));
        }
        mx0 = fmaxf(mx0, __shfl_xor_sync(0xffffffffu, mx0, 1));
        mx0 = fmaxf(mx0, __shfl_xor_sync(0xffffffffu, mx0, 2));
        mx1 = fmaxf(mx1, __shfl_xor_sync(0xffffffffu, mx1, 1));
        mx1 = fmaxf(mx1, __shfl_xor_sync(0xffffffffu, mx1, 2));

        const float mn0 = fmaxf(m0, mx0), mn1 = fmaxf(m1, mx1);
        const float a0 = exp2f(m0 - mn0), a1 = exp2f(m1 - mn1);
        m0 = mn0; m1 = mn1;
        l0 *= a0; l1 *= a1;
#pragma unroll
        for (int dt = 0; dt < 8; dt++) {
            o[dt][0] *= a0; o[dt][1] *= a0;
            o[dt][2] *= a1; o[dt][3] *= a1;
        }

        uint32_t phx[8][2], plx[8][2];
#pragma unroll
        for (int nt = 0; nt < 8; nt++) {
            const float p0 = exp2f(s[nt][0] - mn0), p1 = exp2f(s[nt][1] - mn0);
            const float p2 = exp2f(s[nt][2] - mn1), p3 = exp2f(s[nt][3] - mn1);
            l0 += p0 + p1; l1 += p2 + p3;
            split_pack(p0, p1, phx[nt][0], plx[nt][0]);
            split_pack(p2, p3, phx[nt][1], plx[nt][1]);
        }

#pragma unroll
        for (int ks = 0; ks < 4; ks++) {
            uint32_t pa_h[4] = {phx[2*ks][0], phx[2*ks][1], phx[2*ks+1][0], phx[2*ks+1][1]};
            uint32_t pa_l[4] = {plx[2*ks][0], plx[2*ks][1], plx[2*ks+1][0], plx[2*ks+1][1]};
#pragma unroll
            for (int p = 0; p < 4; p++) {
                const int row = ks * 16 + vkrow;
                const uint32_t bd = (uint32_t)(row * 128) +
                    (((uint32_t)((p * 2 + vdsel) * 16)) ^ ((uint32_t)(row & 7) << 4));
                LDSM4T(fb[2*p][0], fb[2*p][1], fb[2*p+1][0], fb[2*p+1][1], sb + 16384 + bd);
            }
            // pass 1: ph * Vh  (8 independent accumulators)
#pragma unroll
            for (int dt = 0; dt < 8; dt++)
                MMA16816(o[dt], pa_h, fb[dt][0], fb[dt][1]);
            // pass 2: pl * Vh
#pragma unroll
            for (int dt = 0; dt < 8; dt++)
                MMA16816(o[dt], pa_l, fb[dt][0], fb[dt][1]);
#pragma unroll
            for (int p = 0; p < 4; p++) {
                const int row = ks * 16 + vkrow;
                const uint32_t bd = (uint32_t)(row * 128) +
                    (((uint32_t)((p * 2 + vdsel) * 16)) ^ ((uint32_t)(row & 7) << 4));
                LDSM4T(fb[2*p][0], fb[2*p][1], fb[2*p+1][0], fb[2*p+1][1], sb + 24576 + bd);
            }
            // pass 3: ph * Vl
#pragma unroll
            for (int dt = 0; dt < 8; dt++)
                MMA16816(o[dt], pa_h, fb[dt][0], fb[dt][1]);
        }
        __syncthreads();
    }

    l0 += __shfl_xor_sync(0xffffffffu, l0, 1);
    l0 += __shfl_xor_sync(0xffffffffu, l0, 2);
    l1 += __shfl_xor_sync(0xffffffffu, l1, 1);
    l1 += __shfl_xor_sync(0xffffffffu, l1, 2);
    const float i0 = 1.f / l0, i1 = 1.f / l1;

    const size_t or0 = (size_t)(b * T_DIM + q0 + wm0 + g) * C_DIM + h * DK;
    const size_t or1 = or0 + 8 * (size_t)C_DIM;
#pragma unroll
    for (int dt = 0; dt < 8; dt++) {
        const int col = dt * 8 + qd * 2;
        uint32_t hp, lp;
        split_pack(o[dt][0] * i0, o[dt][1] * i0, hp, lp);
        *(uint32_t*)(OH + or0 + col) = hp;
        *(uint32_t*)(OL + or0 + col) = lp;
        split_pack(o[dt][2] * i1, o[dt][3] * i1, hp, lp);
        *(uint32_t*)(OH + or1 + col) = hp;
        *(uint32_t*)(OL + or1 + col) = lp;
    }
}

// ---------------- batched transpose + split (8 x 1024x1024 weights) --------
struct TW8 {
    const float* w[8];
    bf16* th[8];
    bf16* tl[8];
};

__global__ __launch_bounds__(256) void transpose_split8(TW8 tw)
{
    __shared__ float tile[32][33];
    const int z = blockIdx.z;
    const float* __restrict__ W = tw.w[z];
    bf16* __restrict__ Th = tw.th[z];
    bf16* __restrict__ Tl = tw.tl[z];
    const int tx = threadIdx.x, ty = threadIdx.y;
    const int n = blockIdx.x * 32 + tx;
    const int k = blockIdx.y * 32 + ty;
#pragma unroll
    for (int j = 0; j < 4; j++)
        tile[ty + j * 8][tx] = W[(size_t)(k + j * 8) * 1024 + n];
    __syncthreads();
    const int n2 = blockIdx.x * 32 + ty;
    const int k2 = blockIdx.y * 32 + tx;
#pragma unroll
    for (int j = 0; j < 4; j++) {
        float v = tile[tx][ty + j * 8];
        bf16 h, l;
        split2(v, h, l);
        Th[(size_t)(n2 + j * 8) * 1024 + k2] = h;
        Tl[(size_t)(n2 + j * 8) * 1024 + k2] = l;
    }
}

// general transpose_split (FFN weights)
__global__ __launch_bounds__(256) void transpose_split(
    const float* __restrict__ W, bf16* __restrict__ Th, bf16* __restrict__ Tl,
    int Krows, int Ncols)
{
    __shared__ float tile[32][33];
    const int tx = threadIdx.x, ty = threadIdx.y;
    const int n = blockIdx.x * 32 + tx;
    const int k = blockIdx.y * 32 + ty;
#pragma unroll
    for (int j = 0; j < 4; j++)
        tile[ty + j * 8][tx] = W[(size_t)(k + j * 8) * Ncols + n];
    __syncthreads();
    const int n2 = blockIdx.x * 32 + ty;
    const int k2 = blockIdx.y * 32 + tx;
#pragma unroll
    for (int j = 0; j < 4; j++) {
        float v = tile[tx][ty + j * 8];
        bf16 h, l;
        split2(v, h, l);
        Th[(size_t)(n2 + j * 8) * Krows + k2] = h;
        Tl[(size_t)(n2 + j * 8) * Krows + k2] = l;
    }
}

// ---------------- batched elementwise split (dst + src) ---------------------
__global__ __launch_bounds__(256) void split2_kernel(
    const float* __restrict__ x0, bf16* __restrict__ h0, bf16* __restrict__ l0v,
    const float* __restrict__ x1, bf16* __restrict__ h1, bf16* __restrict__ l1v)
{
    const float* x = blockIdx.y ? x1 : x0;
    bf16* hh = blockIdx.y ? h1 : h0;
    bf16* ll = blockIdx.y ? l1v : l0v;
    const int i = (blockIdx.x * 256 + threadIdx.x) * 4;
    float4 v = *(const float4*)(x + i);
    uint32_t hp, lp;
    split_pack(v.x, v.y, hp, lp);
    *(uint32_t*)(hh + i) = hp;
    *(uint32_t*)(ll + i) = lp;
    split_pack(v.z, v.w, hp, lp);
    *(uint32_t*)(hh + i + 2) = hp;
    *(uint32_t*)(ll + i + 2) = lp;
}

// ---------------- fused residual add + LayerNorm (+ optional bf16 split) ----
__global__ __launch_bounds__(256) void add_ln_kernel(
    const float* __restrict__ res, const float* __restrict__ dlt,
    const float* __restrict__ gg, const float* __restrict__ bb,
    float* __restrict__ out, bf16* __restrict__ oh, bf16* __restrict__ ol)
{
    __shared__ float sh_s[8], sh_q[8];
    const int row = blockIdx.x;
    const int tid = threadIdx.x;

    const float4 rv = *(const float4*)(res + (size_t)row * C_DIM + tid * 4);
    const float4 dv = *(const float4*)(dlt + (size_t)row * C_DIM + tid * 4);
    const float x0 = rv.x + dv.x, x1 = rv.y + dv.y;
    const float x2 = rv.z + dv.z, x3 = rv.w + dv.w;

    float s  = x0 + x1 + x2 + x3;
    float ss = x0*x0 + x1*x1 + x2*x2 + x3*x3;
#pragma unroll
    for (int off = 16; off > 0; off >>= 1) {
        s  += __shfl_xor_sync(0xffffffffu, s,  off);
        ss += __shfl_xor_sync(0xffffffffu, ss, off);
    }
    if ((tid & 31) == 0) { sh_s[tid >> 5] = s; sh_q[tid >> 5] = ss; }
    __syncthreads();
    s = 0.f; ss = 0.f;
#pragma unroll
    for (int w = 0; w < 8; w++) { s += sh_s[w]; ss += sh_q[w]; }

    const float mu   = s * (1.f / (float)C_DIM);
    const float var  = ss * (1.f / (float)C_DIM) - mu * mu;
    const float rstd = rsqrtf(var + 1e-12f);

    const float4 gv = *(const float4*)(gg + tid * 4);
    const float4 bv = *(const float4*)(bb + tid * 4);
    float4 ov;
    ov.x = (x0 - mu) * rstd * gv.x + bv.x;
    ov.y = (x1 - mu) * rstd * gv.y + bv.y;
    ov.z = (x2 - mu) * rstd * gv.z + bv.z;
    ov.w = (x3 - mu) * rstd * gv.w + bv.w;
    *(float4*)(out + (size_t)row * C_DIM + tid * 4) = ov;

    if (oh) {
        const size_t ib = (size_t)row * C_DIM + tid * 4;
        uint32_t hp, lp;
        split_pack(ov.x, ov.y, hp, lp);
        *(uint32_t*)(oh + ib) = hp;
        *(uint32_t*)(ol + ib) = lp;
        split_pack(ov.z, ov.w, hp, lp);
        *(uint32_t*)(oh + ib + 2) = hp;
        *(uint32_t*)(ol + ib + 2) = lp;
    }
}

// ---------------- launch ----------------------------------------------------
extern "C" void kernel_launch(void* const* d_in, const int* in_sizes, int n_in,
                              void* d_out, int out_size)
{
    const float* src = (const float*)d_in[0];
    const float* dst = (const float*)d_in[1];
    const float* sa_wq = (const float*)d_in[4];
    const float* sa_wk = (const float*)d_in[5];
    const float* sa_wv = (const float*)d_in[6];
    const float* sa_wo = (const float*)d_in[7];
    const float* sa_bq = (const float*)d_in[8];
    const float* sa_bk = (const float*)d_in[9];
    const float* sa_bv = (const float*)d_in[10];
    const float* sa_bo = (const float*)d_in[11];
    const float* ca_wq = (const float*)d_in[12];
    const float* ca_wk = (const float*)d_in[13];
    const float* ca_wv = (const float*)d_in[14];
    const float* ca_wo = (const float*)d_in[15];
    const float* ca_bq = (const float*)d_in[16];
    const float* ca_bk = (const float*)d_in[17];
    const float* ca_bv = (const float*)d_in[18];
    const float* ca_bo = (const float*)d_in[19];
    const float* ffn_w1 = (const float*)d_in[20];
    const float* ffn_b1 = (const float*)d_in[21];
    const float* ffn_w2 = (const float*)d_in[22];
    const float* ffn_b2 = (const float*)d_in[23];
    const float* ln1_g = (const float*)d_in[24];
    const float* ln1_b = (const float*)d_in[25];
    const float* ln2_g = (const float*)d_in[26];
    const float* ln2_b = (const float*)d_in[27];
    const float* ln3_g = (const float*)d_in[28];
    const float* ln3_b = (const float*)d_in[29];

    float *bo, *by, *by2;
    bf16 *qh, *ql, *kh, *kl, *vh, *vl;
    bf16 *dsth, *dstl, *srch, *srcl, *yh, *yl, *y2h, *y2l, *ath, *atl, *ffh, *ffl, *wth, *wtl;
    cudaGetSymbolAddress((void**)&bo,  g_o);
    cudaGetSymbolAddress((void**)&by,  g_y);
    cudaGetSymbolAddress((void**)&by2, g_y2);
    cudaGetSymbolAddress((void**)&qh,  g_qh);
    cudaGetSymbolAddress((void**)&ql,  g_ql);
    cudaGetSymbolAddress((void**)&kh,  g_kh);
    cudaGetSymbolAddress((void**)&kl,  g_kl);
    cudaGetSymbolAddress((void**)&vh,  g_vh);
    cudaGetSymbolAddress((void**)&vl,  g_vl);
    cudaGetSymbolAddress((void**)&dsth, g_dsth);
    cudaGetSymbolAddress((void**)&dstl, g_dstl);
    cudaGetSymbolAddress((void**)&srch, g_srch);
    cudaGetSymbolAddress((void**)&srcl, g_srcl);
    cudaGetSymbolAddress((void**)&yh,  g_yh);
    cudaGetSymbolAddress((void**)&yl,  g_yl);
    cudaGetSymbolAddress((void**)&y2h, g_y2h);
    cudaGetSymbolAddress((void**)&y2l, g_y2l);
    cudaGetSymbolAddress((void**)&ath, g_ath);
    cudaGetSymbolAddress((void**)&atl, g_atl);
    cudaGetSymbolAddress((void**)&ffh, g_ffh);
    cudaGetSymbolAddress((void**)&ffl, g_ffl);
    cudaGetSymbolAddress((void**)&wth, g_wth);
    cudaGetSymbolAddress((void**)&wtl, g_wtl);

    const size_t SMB = 2 * GSTAGE + 1024;        // GEMM: 65 KB (2 CTAs/SM)
    const size_t SMA = 3 * 32768 + 1024;         // attention: 97 KB
    cudaFuncSetAttribute(gemm_hmma, cudaFuncAttributeMaxDynamicSharedMemorySize, (int)SMB);
    cudaFuncSetAttribute(attention_hmma, cudaFuncAttributeMaxDynamicSharedMemorySize, (int)SMA);

    const size_t OW = 1024 * 1024;
    bf16 *t_sa_wq = wth + 0*OW, *t_sa_wk = wth + 1*OW, *t_sa_wv = wth + 2*OW, *t_sa_wo = wth + 3*OW;
    bf16 *t_ca_wq = wth + 4*OW, *t_ca_wk = wth + 5*OW, *t_ca_wv = wth + 6*OW, *t_ca_wo = wth + 7*OW;
    bf16 *t_w1 = wth + 8*OW, *t_w2 = wth + 12*OW;
    bf16 *u_sa_wq = wtl + 0*OW, *u_sa_wk = wtl + 1*OW, *u_sa_wv = wtl + 2*OW, *u_sa_wo = wtl + 3*OW;
    bf16 *u_ca_wq = wtl + 4*OW, *u_ca_wk = wtl + 5*OW, *u_ca_wv = wtl + 6*OW, *u_ca_wo = wtl + 7*OW;
    bf16 *u_w1 = wtl + 8*OW, *u_w2 = wtl + 12*OW;

    TW8 tw;
    tw.w[0] = sa_wq; tw.th[0] = t_sa_wq; tw.tl[0] = u_sa_wq;
    tw.w[1] = sa_wk; tw.th[1] = t_sa_wk; tw.tl[1] = u_sa_wk;
    tw.w[2] = sa_wv; tw.th[2] = t_sa_wv; tw.tl[2] = u_sa_wv;
    tw.w[3] = sa_wo; tw.th[3] = t_sa_wo; tw.tl[3] = u_sa_wo;
    tw.w[4] = ca_wq; tw.th[4] = t_ca_wq; tw.tl[4] = u_ca_wq;
    tw.w[5] = ca_wk; tw.th[5] = t_ca_wk; tw.tl[5] = u_ca_wk;
    tw.w[6] = ca_wv; tw.th[6] = t_ca_wv; tw.tl[6] = u_ca_wv;
    tw.w[7] = ca_wo; tw.th[7] = t_ca_wo; tw.tl[7] = u_ca_wo;

    const dim3 tb(32, 8);
    transpose_split8<<<dim3(32, 32, 8), tb>>>(tw);
    transpose_split<<<dim3(128, 32), tb>>>(ffn_w1, t_w1, u_w1, 1024, 4096);
    transpose_split<<<dim3(32, 128), tb>>>(ffn_w2, t_w2, u_w2, 4096, 1024);

    split2_kernel<<<dim3(4096, 2), 256>>>(dst, dsth, dstl, src, srch, srcl);

    const dim3 gProj(C_DIM / 128, M_ROWS / 128);     // (8, 32)  = 256 CTAs
    const dim3 gFfn1(DFF_DIM / 128, M_ROWS / 128);   // (32, 32) = 1024 CTAs
    const dim3 gAttn(T_DIM / 128, H_DIM, B_DIM);     // (8, 16, 4)

    // ---- self attention (causal) ----
    gemm_hmma<<<gProj, 256, SMB>>>(dsth, dstl, t_sa_wq, u_sa_wq, sa_bq, nullptr, qh, ql, M_ROWS, C_DIM, C_DIM, 0, QSCALE);
    gemm_hmma<<<gProj, 256, SMB>>>(dsth, dstl, t_sa_wk, u_sa_wk, sa_bk, nullptr, kh, kl, M_ROWS, C_DIM, C_DIM, 0, 1.f);
    gemm_hmma<<<gProj, 256, SMB>>>(dsth, dstl, t_sa_wv, u_sa_wv, sa_bv, nullptr, vh, vl, M_ROWS, C_DIM, C_DIM, 0, 1.f);
    attention_hmma<<<gAttn, 256, SMA>>>(qh, ql, kh, kl, vh, vl, ath, atl, 1);
    gemm_hmma<<<gProj, 256, SMB>>>(ath, atl, t_sa_wo, u_sa_wo, sa_bo, bo, nullptr, nullptr, M_ROWS, C_DIM, C_DIM, 0, 1.f);
    add_ln_kernel<<<M_ROWS, 256>>>(dst, bo, ln1_g, ln1_b, by, yh, yl);

    // ---- cross attention (no mask) ----
    gemm_hmma<<<gProj, 256, SMB>>>(yh, yl, t_ca_wq, u_ca_wq, ca_bq, nullptr, qh, ql, M_ROWS, C_DIM, C_DIM, 0, QSCALE);
    gemm_hmma<<<gProj, 256, SMB>>>(srch, srcl, t_ca_wk, u_ca_wk, ca_bk, nullptr, kh, kl, M_ROWS, C_DIM, C_DIM, 0, 1.f);
    gemm_hmma<<<gProj, 256, SMB>>>(srch, srcl, t_ca_wv, u_ca_wv, ca_bv, nullptr, vh, vl, M_ROWS, C_DIM, C_DIM, 0, 1.f);
    attention_hmma<<<gAttn, 256, SMA>>>(qh, ql, kh, kl, vh, vl, ath, atl, 0);
    gemm_hmma<<<gProj, 256, SMB>>>(ath, atl, t_ca_wo, u_ca_wo, ca_bo, bo, nullptr, nullptr, M_ROWS, C_DIM, C_DIM, 0, 1.f);
    add_ln_kernel<<<M_ROWS, 256>>>(by, bo, ln2_g, ln2_b, by2, y2h, y2l);

    // ---- FFN ----
    gemm_hmma<<<gFfn1, 256, SMB>>>(y2h, y2l, t_w1, u_w1, ffn_b1, nullptr, ffh, ffl, M_ROWS, DFF_DIM, C_DIM, 1, 1.f);
    gemm_hmma<<<gProj, 256, SMB>>>(ffh, ffl, t_w2, u_w2, ffn_b2, bo, nullptr, nullptr, M_ROWS, C_DIM, DFF_DIM, 0, 1.f);
    add_ln_kernel<<<M_ROWS, 256>>>(by2, bo, ln3_g, ln3_b, (float*)d_out, nullptr, nullptr);
}

// round 15
// speedup vs baseline: 1.0233x; 1.0233x over previous
#include <cuda_runtime.h>
#include <cuda_bf16.h>
#include <math.h>
#include <stdint.h>

typedef __nv_bfloat16 bf16;

#define C_DIM   1024
#define T_DIM   1024
#define B_DIM   4
#define H_DIM   16
#define DK      64
#define DFF_DIM 4096
#define M_ROWS  4096

// Q pre-scale: 1/sqrt(dk) * log2(e)  (softmax via exp2)
#define QSCALE 0.1803368801111244f

// ---------------- scratch (device globals; no allocation allowed) ----------
__device__ float g_o [M_ROWS * C_DIM];
__device__ float g_y [M_ROWS * C_DIM];
__device__ float g_y2[M_ROWS * C_DIM];

__device__ bf16 g_qh [M_ROWS * C_DIM], g_ql [M_ROWS * C_DIM];
__device__ bf16 g_kh [M_ROWS * C_DIM], g_kl [M_ROWS * C_DIM];
__device__ bf16 g_vh [M_ROWS * C_DIM], g_vl [M_ROWS * C_DIM];
__device__ bf16 g_dsth[M_ROWS * C_DIM], g_dstl[M_ROWS * C_DIM];
__device__ bf16 g_srch[M_ROWS * C_DIM], g_srcl[M_ROWS * C_DIM];
__device__ bf16 g_yh  [M_ROWS * C_DIM], g_yl  [M_ROWS * C_DIM];
__device__ bf16 g_y2h [M_ROWS * C_DIM], g_y2l [M_ROWS * C_DIM];
__device__ bf16 g_ath [M_ROWS * C_DIM], g_atl [M_ROWS * C_DIM];
__device__ bf16 g_ffh [M_ROWS * DFF_DIM], g_ffl[M_ROWS * DFF_DIM];
__device__ bf16 g_wth [16 * 1024 * 1024], g_wtl[16 * 1024 * 1024];

// ---------------- PTX helpers (plain sm_103: no tcgen05/TMEM) --------------
__device__ __forceinline__ uint32_t smem_u32(const void* p) {
    uint32_t a;
    asm("{ .reg .u64 t; cvta.to.shared.u64 t, %1; cvt.u32.u64 %0, t; }" : "=r"(a) : "l"(p));
    return a;
}
#define SMEM_SWIZZLE_128B(o) ((o) ^ (((o) >> 3) & 0x70))

#define CP16(dst, src) \
    asm volatile("cp.async.cg.shared.global [%0], [%1], 16;" :: "r"(dst), "l"(src) : "memory")
#define CP_COMMIT() asm volatile("cp.async.commit_group;" ::: "memory")
#define CP_WAIT(n)  asm volatile("cp.async.wait_group %0;" :: "n"(n) : "memory")

#define LDSM4(r0, r1, r2, r3, a) \
    asm volatile("ldmatrix.sync.aligned.m8n8.x4.shared.b16 {%0,%1,%2,%3}, [%4];" \
                 : "=r"(r0), "=r"(r1), "=r"(r2), "=r"(r3) : "r"(a))
#define LDSM4T(r0, r1, r2, r3, a) \
    asm volatile("ldmatrix.sync.aligned.m8n8.x4.trans.shared.b16 {%0,%1,%2,%3}, [%4];" \
                 : "=r"(r0), "=r"(r1), "=r"(r2), "=r"(r3) : "r"(a))

#define MMA16816(d, a, b0, b1) \
    asm volatile("mma.sync.aligned.m16n8k16.row.col.f32.bf16.bf16.f32 " \
                 "{%0,%1,%2,%3}, {%4,%5,%6,%7}, {%8,%9}, {%0,%1,%2,%3};" \
                 : "+f"((d)[0]), "+f"((d)[1]), "+f"((d)[2]), "+f"((d)[3]) \
                 : "r"((a)[0]), "r"((a)[1]), "r"((a)[2]), "r"((a)[3]), "r"(b0), "r"(b1))

__device__ __forceinline__ void split2(float v, bf16& h, bf16& l) {
    h = __float2bfloat16(v);
    l = __float2bfloat16(v - __bfloat162float(h));
}
__device__ __forceinline__ void split_pack(float x, float y, uint32_t& hp, uint32_t& lp) {
    bf16 hx, lx, hy, ly;
    split2(x, hx, lx);
    split2(y, hy, ly);
    __nv_bfloat162 h2(hx, hy), l2(lx, ly);
    hp = *(uint32_t*)&h2;
    lp = *(uint32_t*)&l2;
}

// ---------------- HMMA GEMM (R8/R13-frozen): CTA 128x128, BK=32, 8 warps ---
// 2 CTAs/SM: stage 32KB (4 regions x 8KB, 64B rows), double-buffered.
// 64B-row swizzle: chunk' = chunk ^ ((row>>1)&3)  (conflict-free ldmatrix).
#define GSTAGE 32768

__global__ __launch_bounds__(256, 2) void gemm_hmma(
    const bf16* __restrict__ Ah, const bf16* __restrict__ Al,
    const bf16* __restrict__ Bh, const bf16* __restrict__ Bl,
    const float* __restrict__ bias,
    float* __restrict__ outF, bf16* __restrict__ outH, bf16* __restrict__ outL,
    int M, int N, int K, int do_gelu, float oscale)
{
    extern __shared__ char dynsm[];
    const uint32_t sb0 = (smem_u32(dynsm) + 1023) & ~1023u;

    const int tid = threadIdx.x;
    const int m0 = blockIdx.y * 128;
    const int n0 = blockIdx.x * 128;
    const int w = tid >> 5, lane = tid & 31;
    const int wm0 = (w >> 2) * 64;
    const int wn0 = (w & 3) * 32;

    const int lr = tid >> 1;
    const int lc = (tid & 1) * 2;

    const int arow = lane & 15;
    const int ahalf = lane >> 4;
    const int brow = ((lane >> 4) & 1) * 8 + (lane & 7);
    const int bhalf = (lane >> 3) & 1;

    float acc[4][4][4];
#pragma unroll
    for (int i = 0; i < 4; i++)
#pragma unroll
        for (int j = 0; j < 4; j++)
#pragma unroll
            for (int r = 0; r < 4; r++) acc[i][j][r] = 0.f;

    const int NC = K >> 5;

    auto load_stage = [&](uint32_t sb, int k0) {
        const bf16* pa_h = Ah + (size_t)(m0 + lr) * K + k0 + lc * 8;
        const bf16* pa_l = Al + (size_t)(m0 + lr) * K + k0 + lc * 8;
        const bf16* pb_h = Bh + (size_t)(n0 + lr) * K + k0 + lc * 8;
        const bf16* pb_l = Bl + (size_t)(n0 + lr) * K + k0 + lc * 8;
        const uint32_t sw = (uint32_t)((lr >> 1) & 3);
#pragma unroll
        for (int j = 0; j < 2; j++) {
            const uint32_t off = (uint32_t)(lr * 64) + ((((uint32_t)(lc + j)) ^ sw) << 4);
            CP16(sb + off,         pa_h + j * 8);
            CP16(sb + 8192  + off, pa_l + j * 8);
            CP16(sb + 16384 + off, pb_h + j * 8);
            CP16(sb + 24576 + off, pb_l + j * 8);
        }
    };

    load_stage(sb0, 0);
    CP_COMMIT();

    for (int c = 0; c < NC; c++) {
        if (c + 1 < NC) {
            load_stage(sb0 + ((c + 1) & 1) * GSTAGE, (c + 1) * 32);
            CP_COMMIT();
            CP_WAIT(1);
        } else {
            CP_WAIT(0);
        }
        __syncthreads();

        const uint32_t sb = sb0 + (c & 1) * GSTAGE;
        const uint32_t sAh = sb, sAl = sb + 8192, sBh = sb + 16384, sBl = sb + 24576;

#pragma unroll
        for (int ks = 0; ks < 2; ks++) {
            uint32_t ah[4][4], al[4][4];
#pragma unroll
            for (int mt = 0; mt < 4; mt++) {
                const int row = wm0 + mt * 16 + arow;
                const uint32_t chunk = (uint32_t)(ks * 2 + ahalf);
                const uint32_t ad = (uint32_t)(row * 64) +
                                    ((chunk ^ ((uint32_t)(row >> 1) & 3)) << 4);
                LDSM4(ah[mt][0], ah[mt][1], ah[mt][2], ah[mt][3], sAh + ad);
                LDSM4(al[mt][0], al[mt][1], al[mt][2], al[mt][3], sAl + ad);
            }
            uint32_t fb[4][2];
            uint32_t bd0, bd1;
            {
                const int r0 = wn0 + brow, r1 = wn0 + 16 + brow;
                const uint32_t chunk = (uint32_t)(ks * 2 + bhalf);
                bd0 = (uint32_t)(r0 * 64) + ((chunk ^ ((uint32_t)(r0 >> 1) & 3)) << 4);
                bd1 = (uint32_t)(r1 * 64) + ((chunk ^ ((uint32_t)(r1 >> 1) & 3)) << 4);
            }
            LDSM4(fb[0][0], fb[0][1], fb[1][0], fb[1][1], sBh + bd0);
            LDSM4(fb[2][0], fb[2][1], fb[3][0], fb[3][1], sBh + bd1);
#pragma unroll
            for (int mt = 0; mt < 4; mt++)
#pragma unroll
                for (int nt = 0; nt < 4; nt++) {
                    MMA16816(acc[mt][nt], ah[mt], fb[nt][0], fb[nt][1]);
                    MMA16816(acc[mt][nt], al[mt], fb[nt][0], fb[nt][1]);
                }
            // reuse fb registers for B-lo
            LDSM4(fb[0][0], fb[0][1], fb[1][0], fb[1][1], sBl + bd0);
            LDSM4(fb[2][0], fb[2][1], fb[3][0], fb[3][1], sBl + bd1);
#pragma unroll
            for (int mt = 0; mt < 4; mt++)
#pragma unroll
                for (int nt = 0; nt < 4; nt++)
                    MMA16816(acc[mt][nt], ah[mt], fb[nt][0], fb[nt][1]);
        }
        __syncthreads();
    }

    const int g = lane >> 2, q = lane & 3;
#pragma unroll
    for (int mt = 0; mt < 4; mt++) {
#pragma unroll
        for (int half = 0; half < 2; half++) {
            const int row = m0 + wm0 + mt * 16 + half * 8 + g;
#pragma unroll
            for (int nt = 0; nt < 4; nt++) {
                const int col = n0 + wn0 + nt * 8 + q * 2;
                float v0 = acc[mt][nt][half * 2 + 0] + __ldg(bias + col);
                float v1 = acc[mt][nt][half * 2 + 1] + __ldg(bias + col + 1);
                if (do_gelu) {
                    v0 = 0.5f * v0 * (1.f + erff(v0 * 0.70710678118654752f));
                    v1 = 0.5f * v1 * (1.f + erff(v1 * 0.70710678118654752f));
                }
                const size_t idx = (size_t)row * N + col;
                if (outF) *(float2*)(outF + idx) = make_float2(v0, v1);
                if (outH) {
                    uint32_t hp, lp;
                    split_pack(v0 * oscale, v1 * oscale, hp, lp);
                    *(uint32_t*)(outH + idx) = hp;
                    *(uint32_t*)(outL + idx) = lp;
                }
            }
        }
    }
}

// ---------------- HMMA flash attention: 128 threads, 64 q-rows, occ-2 ------
// grid (T/64, H, B), 4 warps x 16 q-rows. Q pre-scaled. Q smem 16KB +
// 2 KV stages x 32KB = 81KB -> 2 CTAs/SM (128 thr => 256-reg budget, no spill).
__global__ __launch_bounds__(128, 2) void attention_hmma(
    const bf16* __restrict__ Qh, const bf16* __restrict__ Ql,
    const bf16* __restrict__ Kh, const bf16* __restrict__ Kl,
    const bf16* __restrict__ Vh, const bf16* __restrict__ Vl,
    bf16* __restrict__ OH, bf16* __restrict__ OL,
    int causal)
{
    extern __shared__ char dynsm[];
    const uint32_t sQ  = (smem_u32(dynsm) + 1023) & ~1023u;   // Qh 8K | Ql 8K
    const uint32_t sKV = sQ + 16384;                          // 2 stages x 32K

    const int tid = threadIdx.x;
    const int w = tid >> 5, lane = tid & 31;
    const int b = blockIdx.z, h = blockIdx.y;
    const int q0 = blockIdx.x * 64;
    const int wm0 = w * 16;
    const int g = lane >> 2, qd = lane & 3;

    // Q tile: 64 rows x 128B (hi + lo)
    {
        const int r = tid >> 1, c0 = (tid & 1) * 4;
        const size_t qrow = (size_t)(b * T_DIM + q0 + r) * C_DIM + h * DK;
#pragma unroll
        for (int c = c0; c < c0 + 4; c++) {
            const uint32_t off = SMEM_SWIZZLE_128B((uint32_t)(r * 128 + c * 16));
            CP16(sQ + off,        Qh + qrow + c * 8);
            CP16(sQ + 8192 + off, Ql + qrow + c * 8);
        }
    }
    // KV tile: 64 rows x 128B x 4 regions; 16 CP16 per thread
    auto load_kv = [&](uint32_t sb, int k0) {
        const int r = tid >> 1, c0 = (tid & 1) * 4;
        const size_t krow = (size_t)(b * T_DIM + k0 + r) * C_DIM + h * DK;
#pragma unroll
        for (int c = c0; c < c0 + 4; c++) {
            const uint32_t off = SMEM_SWIZZLE_128B((uint32_t)(r * 128 + c * 16));
            CP16(sb + off,         Kh + krow + c * 8);
            CP16(sb + 8192  + off, Kl + krow + c * 8);
            CP16(sb + 16384 + off, Vh + krow + c * 8);
            CP16(sb + 24576 + off, Vl + krow + c * 8);
        }
    };
    load_kv(sKV, 0);
    CP_COMMIT();

    const int ntiles = causal ? (q0 + 64) / 64 : (T_DIM / 64);

    float m0 = -1e30f, m1 = -1e30f, l0 = 0.f, l1 = 0.f;
    float o[8][4];
#pragma unroll
    for (int i = 0; i < 8; i++)
#pragma unroll
        for (int j = 0; j < 4; j++) o[i][j] = 0.f;

    uint32_t fqh[4][4], fql[4][4];
    const int arow = lane & 15, ahalf = lane >> 4;
    const int brow = ((lane >> 4) & 1) * 8 + (lane & 7), bhalf = (lane >> 3) & 1;
    const int vkrow = ((lane >> 3) & 1) * 8 + (lane & 7);
    const int vdsel = lane >> 4;

    for (int it = 0; it < ntiles; it++) {
        if (it + 1 < ntiles) {
            load_kv(sKV + ((it + 1) & 1) * 32768, (it + 1) * 64);
            CP_COMMIT();
            CP_WAIT(1);
        } else {
            CP_WAIT(0);
        }
        __syncthreads();

        if (it == 0) {
#pragma unroll
            for (int ks = 0; ks < 4; ks++) {
                const int row = wm0 + arow;
                const uint32_t ad = (uint32_t)(row * 128) +
                    (((uint32_t)(ks * 32 + ahalf * 16)) ^ ((uint32_t)(row & 7) << 4));
                LDSM4(fqh[ks][0], fqh[ks][1], fqh[ks][2], fqh[ks][3], sQ + ad);
                LDSM4(fql[ks][0], fql[ks][1], fql[ks][2], fql[ks][3], sQ + 8192 + ad);
            }
        }

        const uint32_t sb = sKV + (it & 1) * 32768;

        float s[8][4];
#pragma unroll
        for (int i = 0; i < 8; i++)
#pragma unroll
            for (int j = 0; j < 4; j++) s[i][j] = 0.f;

        uint32_t fb[8][2];
#pragma unroll
        for (int ks = 0; ks < 4; ks++) {
#pragma unroll
            for (int ng = 0; ng < 4; ng++) {
                const int row = ng * 16 + brow;
                const uint32_t bd = (uint32_t)(row * 128) +
                    (((uint32_t)(ks * 32 + bhalf * 16)) ^ ((uint32_t)(row & 7) << 4));
                LDSM4(fb[2*ng][0], fb[2*ng][1], fb[2*ng+1][0], fb[2*ng+1][1], sb + bd);
            }
#pragma unroll
            for (int nt = 0; nt < 8; nt++) {
                MMA16816(s[nt], fqh[ks], fb[nt][0], fb[nt][1]);
                MMA16816(s[nt], fql[ks], fb[nt][0], fb[nt][1]);
            }
#pragma unroll
            for (int ng = 0; ng < 4; ng++) {
                const int row = ng * 16 + brow;
                const uint32_t bd = (uint32_t)(row * 128) +
                    (((uint32_t)(ks * 32 + bhalf * 16)) ^ ((uint32_t)(row & 7) << 4));
                LDSM4(fb[2*ng][0], fb[2*ng][1], fb[2*ng+1][0], fb[2*ng+1][1], sb + 8192 + bd);
            }
#pragma unroll
            for (int nt = 0; nt < 8; nt++)
                MMA16816(s[nt], fqh[ks], fb[nt][0], fb[nt][1]);
        }

        const int kbase = it * 64;
        const int row0 = q0 + wm0 + g, row1 = row0 + 8;
        if (causal && kbase + 63 > row0) {
#pragma unroll
            for (int nt = 0; nt < 8; nt++) {
                const int cb = kbase + nt * 8 + qd * 2;
                if (cb     > row0) s[nt][0] = -1e30f;
                if (cb + 1 > row0) s[nt][1] = -1e30f;
                if (cb     > row1) s[nt][2] = -1e30f;
                if (cb + 1 > row1) s[nt][3] = -1e30f;
            }
        }

        float mx0 = -1e30f, mx1 = -1e30f;
#pragma unroll
        for (int nt = 0; nt < 8; nt++) {
            mx0 = fmaxf(mx0, fmaxf(s[nt][0], s[nt][1]));
            mx1 = fmaxf(mx1, fmaxf(s[nt][2], s[nt][3]));
        }
        mx0 = fmaxf(mx0, __shfl_xor_sync(0xffffffffu, mx0, 1));
        mx0 = fmaxf(mx0, __shfl_xor_sync(0xffffffffu, mx0, 2));
        mx1 = fmaxf(mx1, __shfl_xor_sync(0xffffffffu, mx1, 1));
        mx1 = fmaxf(mx1, __shfl_xor_sync(0xffffffffu, mx1, 2));

        const float mn0 = fmaxf(m0, mx0), mn1 = fmaxf(m1, mx1);
        const float a0 = exp2f(m0 - mn0), a1 = exp2f(m1 - mn1);
        m0 = mn0; m1 = mn1;
        l0 *= a0; l1 *= a1;
#pragma unroll
        for (int dt = 0; dt < 8; dt++) {
            o[dt][0] *= a0; o[dt][1] *= a0;
            o[dt][2] *= a1; o[dt][3] *= a1;
        }

        uint32_t phx[8][2], plx[8][2];
#pragma unroll
        for (int nt = 0; nt < 8; nt++) {
            const float p0 = exp2f(s[nt][0] - mn0), p1 = exp2f(s[nt][1] - mn0);
            const float p2 = exp2f(s[nt][2] - mn1), p3 = exp2f(s[nt][3] - mn1);
            l0 += p0 + p1; l1 += p2 + p3;
            split_pack(p0, p1, phx[nt][0], plx[nt][0]);
            split_pack(p2, p3, phx[nt][1], plx[nt][1]);
        }

#pragma unroll
        for (int ks = 0; ks < 4; ks++) {
            uint32_t pa_h[4] = {phx[2*ks][0], phx[2*ks][1], phx[2*ks+1][0], phx[2*ks+1][1]};
            uint32_t pa_l[4] = {plx[2*ks][0], plx[2*ks][1], plx[2*ks+1][0], plx[2*ks+1][1]};
#pragma unroll
            for (int p = 0; p < 4; p++) {
                const int row = ks * 16 + vkrow;
                const uint32_t bd = (uint32_t)(row * 128) +
                    (((uint32_t)((p * 2 + vdsel) * 16)) ^ ((uint32_t)(row & 7) << 4));
                LDSM4T(fb[2*p][0], fb[2*p][1], fb[2*p+1][0], fb[2*p+1][1], sb + 16384 + bd);
            }
#pragma unroll
            for (int dt = 0; dt < 8; dt++) {
                MMA16816(o[dt], pa_h, fb[dt][0], fb[dt][1]);
                MMA16816(o[dt], pa_l, fb[dt][0], fb[dt][1]);
            }
#pragma unroll
            for (int p = 0; p < 4; p++) {
                const int row = ks * 16 + vkrow;
                const uint32_t bd = (uint32_t)(row * 128) +
                    (((uint32_t)((p * 2 + vdsel) * 16)) ^ ((uint32_t)(row & 7) << 4));
                LDSM4T(fb[2*p][0], fb[2*p][1], fb[2*p+1][0], fb[2*p+1][1], sb + 24576 + bd);
            }
#pragma unroll
            for (int dt = 0; dt < 8; dt++)
                MMA16816(o[dt], pa_h, fb[dt][0], fb[dt][1]);
        }
        __syncthreads();
    }

    l0 += __shfl_xor_sync(0xffffffffu, l0, 1);
    l0 += __shfl_xor_sync(0xffffffffu, l0, 2);
    l1 += __shfl_xor_sync(0xffffffffu, l1, 1);
    l1 += __shfl_xor_sync(0xffffffffu, l1, 2);
    const float i0 = 1.f / l0, i1 = 1.f / l1;

    const size_t or0 = (size_t)(b * T_DIM + q0 + wm0 + g) * C_DIM + h * DK;
    const size_t or1 = or0 + 8 * (size_t)C_DIM;
#pragma unroll
    for (int dt = 0; dt < 8; dt++) {
        const int col = dt * 8 + qd * 2;
        uint32_t hp, lp;
        split_pack(o[dt][0] * i0, o[dt][1] * i0, hp, lp);
        *(uint32_t*)(OH + or0 + col) = hp;
        *(uint32_t*)(OL + or0 + col) = lp;
        split_pack(o[dt][2] * i1, o[dt][3] * i1, hp, lp);
        *(uint32_t*)(OH + or1 + col) = hp;
        *(uint32_t*)(OL + or1 + col) = lp;
    }
}

// ---------------- batched transpose + split (8 x 1024x1024 weights) --------
struct TW8 {
    const float* w[8];
    bf16* th[8];
    bf16* tl[8];
};

__global__ __launch_bounds__(256) void transpose_split8(TW8 tw)
{
    __shared__ float tile[32][33];
    const int z = blockIdx.z;
    const float* __restrict__ W = tw.w[z];
    bf16* __restrict__ Th = tw.th[z];
    bf16* __restrict__ Tl = tw.tl[z];
    const int tx = threadIdx.x, ty = threadIdx.y;
    const int n = blockIdx.x * 32 + tx;
    const int k = blockIdx.y * 32 + ty;
#pragma unroll
    for (int j = 0; j < 4; j++)
        tile[ty + j * 8][tx] = W[(size_t)(k + j * 8) * 1024 + n];
    __syncthreads();
    const int n2 = blockIdx.x * 32 + ty;
    const int k2 = blockIdx.y * 32 + tx;
#pragma unroll
    for (int j = 0; j < 4; j++) {
        float v = tile[tx][ty + j * 8];
        bf16 h, l;
        split2(v, h, l);
        Th[(size_t)(n2 + j * 8) * 1024 + k2] = h;
        Tl[(size_t)(n2 + j * 8) * 1024 + k2] = l;
    }
}

// general transpose_split (FFN weights)
__global__ __launch_bounds__(256) void transpose_split(
    const float* __restrict__ W, bf16* __restrict__ Th, bf16* __restrict__ Tl,
    int Krows, int Ncols)
{
    __shared__ float tile[32][33];
    const int tx = threadIdx.x, ty = threadIdx.y;
    const int n = blockIdx.x * 32 + tx;
    const int k = blockIdx.y * 32 + ty;
#pragma unroll
    for (int j = 0; j < 4; j++)
        tile[ty + j * 8][tx] = W[(size_t)(k + j * 8) * Ncols + n];
    __syncthreads();
    const int n2 = blockIdx.x * 32 + ty;
    const int k2 = blockIdx.y * 32 + tx;
#pragma unroll
    for (int j = 0; j < 4; j++) {
        float v = tile[tx][ty + j * 8];
        bf16 h, l;
        split2(v, h, l);
        Th[(size_t)(n2 + j * 8) * Krows + k2] = h;
        Tl[(size_t)(n2 + j * 8) * Krows + k2] = l;
    }
}

// ---------------- batched elementwise split (dst + src) ---------------------
__global__ __launch_bounds__(256) void split2_kernel(
    const float* __restrict__ x0, bf16* __restrict__ h0, bf16* __restrict__ l0v,
    const float* __restrict__ x1, bf16* __restrict__ h1, bf16* __restrict__ l1v)
{
    const float* x = blockIdx.y ? x1 : x0;
    bf16* hh = blockIdx.y ? h1 : h0;
    bf16* ll = blockIdx.y ? l1v : l0v;
    const int i = (blockIdx.x * 256 + threadIdx.x) * 4;
    float4 v = *(const float4*)(x + i);
    uint32_t hp, lp;
    split_pack(v.x, v.y, hp, lp);
    *(uint32_t*)(hh + i) = hp;
    *(uint32_t*)(ll + i) = lp;
    split_pack(v.z, v.w, hp, lp);
    *(uint32_t*)(hh + i + 2) = hp;
    *(uint32_t*)(ll + i + 2) = lp;
}

// ---------------- fused residual add + LayerNorm (+ optional bf16 split) ----
__global__ __launch_bounds__(256) void add_ln_kernel(
    const float* __restrict__ res, const float* __restrict__ dlt,
    const float* __restrict__ gg, const float* __restrict__ bb,
    float* __restrict__ out, bf16* __restrict__ oh, bf16* __restrict__ ol)
{
    __shared__ float sh_s[8], sh_q[8];
    const int row = blockIdx.x;
    const int tid = threadIdx.x;

    const float4 rv = *(const float4*)(res + (size_t)row * C_DIM + tid * 4);
    const float4 dv = *(const float4*)(dlt + (size_t)row * C_DIM + tid * 4);
    const float x0 = rv.x + dv.x, x1 = rv.y + dv.y;
    const float x2 = rv.z + dv.z, x3 = rv.w + dv.w;

    float s  = x0 + x1 + x2 + x3;
    float ss = x0*x0 + x1*x1 + x2*x2 + x3*x3;
#pragma unroll
    for (int off = 16; off > 0; off >>= 1) {
        s  += __shfl_xor_sync(0xffffffffu, s,  off);
        ss += __shfl_xor_sync(0xffffffffu, ss, off);
    }
    if ((tid & 31) == 0) { sh_s[tid >> 5] = s; sh_q[tid >> 5] = ss; }
    __syncthreads();
    s = 0.f; ss = 0.f;
#pragma unroll
    for (int w = 0; w < 8; w++) { s += sh_s[w]; ss += sh_q[w]; }

    const float mu   = s * (1.f / (float)C_DIM);
    const float var  = ss * (1.f / (float)C_DIM) - mu * mu;
    const float rstd = rsqrtf(var + 1e-12f);

    const float4 gv = *(const float4*)(gg + tid * 4);
    const float4 bv = *(const float4*)(bb + tid * 4);
    float4 ov;
    ov.x = (x0 - mu) * rstd * gv.x + bv.x;
    ov.y = (x1 - mu) * rstd * gv.y + bv.y;
    ov.z = (x2 - mu) * rstd * gv.z + bv.z;
    ov.w = (x3 - mu) * rstd * gv.w + bv.w;
    *(float4*)(out + (size_t)row * C_DIM + tid * 4) = ov;

    if (oh) {
        const size_t ib = (size_t)row * C_DIM + tid * 4;
        uint32_t hp, lp;
        split_pack(ov.x, ov.y, hp, lp);
        *(uint32_t*)(oh + ib) = hp;
        *(uint32_t*)(ol + ib) = lp;
        split_pack(ov.z, ov.w, hp, lp);
        *(uint32_t*)(oh + ib + 2) = hp;
        *(uint32_t*)(ol + ib + 2) = lp;
    }
}

// ---------------- launch ----------------------------------------------------
extern "C" void kernel_launch(void* const* d_in, const int* in_sizes, int n_in,
                              void* d_out, int out_size)
{
    const float* src = (const float*)d_in[0];
    const float* dst = (const float*)d_in[1];
    const float* sa_wq = (const float*)d_in[4];
    const float* sa_wk = (const float*)d_in[5];
    const float* sa_wv = (const float*)d_in[6];
    const float* sa_wo = (const float*)d_in[7];
    const float* sa_bq = (const float*)d_in[8];
    const float* sa_bk = (const float*)d_in[9];
    const float* sa_bv = (const float*)d_in[10];
    const float* sa_bo = (const float*)d_in[11];
    const float* ca_wq = (const float*)d_in[12];
    const float* ca_wk = (const float*)d_in[13];
    const float* ca_wv = (const float*)d_in[14];
    const float* ca_wo = (const float*)d_in[15];
    const float* ca_bq = (const float*)d_in[16];
    const float* ca_bk = (const float*)d_in[17];
    const float* ca_bv = (const float*)d_in[18];
    const float* ca_bo = (const float*)d_in[19];
    const float* ffn_w1 = (const float*)d_in[20];
    const float* ffn_b1 = (const float*)d_in[21];
    const float* ffn_w2 = (const float*)d_in[22];
    const float* ffn_b2 = (const float*)d_in[23];
    const float* ln1_g = (const float*)d_in[24];
    const float* ln1_b = (const float*)d_in[25];
    const float* ln2_g = (const float*)d_in[26];
    const float* ln2_b = (const float*)d_in[27];
    const float* ln3_g = (const float*)d_in[28];
    const float* ln3_b = (const float*)d_in[29];

    float *bo, *by, *by2;
    bf16 *qh, *ql, *kh, *kl, *vh, *vl;
    bf16 *dsth, *dstl, *srch, *srcl, *yh, *yl, *y2h, *y2l, *ath, *atl, *ffh, *ffl, *wth, *wtl;
    cudaGetSymbolAddress((void**)&bo,  g_o);
    cudaGetSymbolAddress((void**)&by,  g_y);
    cudaGetSymbolAddress((void**)&by2, g_y2);
    cudaGetSymbolAddress((void**)&qh,  g_qh);
    cudaGetSymbolAddress((void**)&ql,  g_ql);
    cudaGetSymbolAddress((void**)&kh,  g_kh);
    cudaGetSymbolAddress((void**)&kl,  g_kl);
    cudaGetSymbolAddress((void**)&vh,  g_vh);
    cudaGetSymbolAddress((void**)&vl,  g_vl);
    cudaGetSymbolAddress((void**)&dsth, g_dsth);
    cudaGetSymbolAddress((void**)&dstl, g_dstl);
    cudaGetSymbolAddress((void**)&srch, g_srch);
    cudaGetSymbolAddress((void**)&srcl, g_srcl);
    cudaGetSymbolAddress((void**)&yh,  g_yh);
    cudaGetSymbolAddress((void**)&yl,  g_yl);
    cudaGetSymbolAddress((void**)&y2h, g_y2h);
    cudaGetSymbolAddress((void**)&y2l, g_y2l);
    cudaGetSymbolAddress((void**)&ath, g_ath);
    cudaGetSymbolAddress((void**)&atl, g_atl);
    cudaGetSymbolAddress((void**)&ffh, g_ffh);
    cudaGetSymbolAddress((void**)&ffl, g_ffl);
    cudaGetSymbolAddress((void**)&wth, g_wth);
    cudaGetSymbolAddress((void**)&wtl, g_wtl);

    const size_t SMB = 2 * GSTAGE + 1024;        // GEMM: 65 KB (2 CTAs/SM)
    const size_t SMA = 16384 + 2 * 32768 + 1024; // attention: 81 KB (2 CTAs/SM)
    cudaFuncSetAttribute(gemm_hmma, cudaFuncAttributeMaxDynamicSharedMemorySize, (int)SMB);
    cudaFuncSetAttribute(attention_hmma, cudaFuncAttributeMaxDynamicSharedMemorySize, (int)SMA);

    const size_t OW = 1024 * 1024;
    bf16 *t_sa_wq = wth + 0*OW, *t_sa_wk = wth + 1*OW, *t_sa_wv = wth + 2*OW, *t_sa_wo = wth + 3*OW;
    bf16 *t_ca_wq = wth + 4*OW, *t_ca_wk = wth + 5*OW, *t_ca_wv = wth + 6*OW, *t_ca_wo = wth + 7*OW;
    bf16 *t_w1 = wth + 8*OW, *t_w2 = wth + 12*OW;
    bf16 *u_sa_wq = wtl + 0*OW, *u_sa_wk = wtl + 1*OW, *u_sa_wv = wtl + 2*OW, *u_sa_wo = wtl + 3*OW;
    bf16 *u_ca_wq = wtl + 4*OW, *u_ca_wk = wtl + 5*OW, *u_ca_wv = wtl + 6*OW, *u_ca_wo = wtl + 7*OW;
    bf16 *u_w1 = wtl + 8*OW, *u_w2 = wtl + 12*OW;

    TW8 tw;
    tw.w[0] = sa_wq; tw.th[0] = t_sa_wq; tw.tl[0] = u_sa_wq;
    tw.w[1] = sa_wk; tw.th[1] = t_sa_wk; tw.tl[1] = u_sa_wk;
    tw.w[2] = sa_wv; tw.th[2] = t_sa_wv; tw.tl[2] = u_sa_wv;
    tw.w[3] = sa_wo; tw.th[3] = t_sa_wo; tw.tl[3] = u_sa_wo;
    tw.w[4] = ca_wq; tw.th[4] = t_ca_wq; tw.tl[4] = u_ca_wq;
    tw.w[5] = ca_wk; tw.th[5] = t_ca_wk; tw.tl[5] = u_ca_wk;
    tw.w[6] = ca_wv; tw.th[6] = t_ca_wv; tw.tl[6] = u_ca_wv;
    tw.w[7] = ca_wo; tw.th[7] = t_ca_wo; tw.tl[7] = u_ca_wo;

    const dim3 tb(32, 8);
    transpose_split8<<<dim3(32, 32, 8), tb>>>(tw);
    transpose_split<<<dim3(128, 32), tb>>>(ffn_w1, t_w1, u_w1, 1024, 4096);
    transpose_split<<<dim3(32, 128), tb>>>(ffn_w2, t_w2, u_w2, 4096, 1024);

    split2_kernel<<<dim3(4096, 2), 256>>>(dst, dsth, dstl, src, srch, srcl);

    const dim3 gProj(C_DIM / 128, M_ROWS / 128);     // (8, 32)  = 256 CTAs
    const dim3 gFfn1(DFF_DIM / 128, M_ROWS / 128);   // (32, 32) = 1024 CTAs
    const dim3 gAttn(T_DIM / 64, H_DIM, B_DIM);      // (16, 16, 4) = 1024 CTAs

    // ---- self attention (causal) ----
    gemm_hmma<<<gProj, 256, SMB>>>(dsth, dstl, t_sa_wq, u_sa_wq, sa_bq, nullptr, qh, ql, M_ROWS, C_DIM, C_DIM, 0, QSCALE);
    gemm_hmma<<<gProj, 256, SMB>>>(dsth, dstl, t_sa_wk, u_sa_wk, sa_bk, nullptr, kh, kl, M_ROWS, C_DIM, C_DIM, 0, 1.f);
    gemm_hmma<<<gProj, 256, SMB>>>(dsth, dstl, t_sa_wv, u_sa_wv, sa_bv, nullptr, vh, vl, M_ROWS, C_DIM, C_DIM, 0, 1.f);
    attention_hmma<<<gAttn, 128, SMA>>>(qh, ql, kh, kl, vh, vl, ath, atl, 1);
    gemm_hmma<<<gProj, 256, SMB>>>(ath, atl, t_sa_wo, u_sa_wo, sa_bo, bo, nullptr, nullptr, M_ROWS, C_DIM, C_DIM, 0, 1.f);
    add_ln_kernel<<<M_ROWS, 256>>>(dst, bo, ln1_g, ln1_b, by, yh, yl);

    // ---- cross attention (no mask) ----
    gemm_hmma<<<gProj, 256, SMB>>>(yh, yl, t_ca_wq, u_ca_wq, ca_bq, nullptr, qh, ql, M_ROWS, C_DIM, C_DIM, 0, QSCALE);
    gemm_hmma<<<gProj, 256, SMB>>>(srch, srcl, t_ca_wk, u_ca_wk, ca_bk, nullptr, kh, kl, M_ROWS, C_DIM, C_DIM, 0, 1.f);
    gemm_hmma<<<gProj, 256, SMB>>>(srch, srcl, t_ca_wv, u_ca_wv, ca_bv, nullptr, vh, vl, M_ROWS, C_DIM, C_DIM, 0, 1.f);
    attention_hmma<<<gAttn, 128, SMA>>>(qh, ql, kh, kl, vh, vl, ath, atl, 0);
    gemm_hmma<<<gProj, 256, SMB>>>(ath, atl, t_ca_wo, u_ca_wo, ca_bo, bo, nullptr, nullptr, M_ROWS, C_DIM, C_DIM, 0, 1.f);
    add_ln_kernel<<<M_ROWS, 256>>>(by, bo, ln2_g, ln2_b, by2, y2h, y2l);

    // ---- FFN ----
    gemm_hmma<<<gFfn1, 256, SMB>>>(y2h, y2l, t_w1, u_w1, ffn_b1, nullptr, ffh, ffl, M_ROWS, DFF_DIM, C_DIM, 1, 1.f);
    gemm_hmma<<<gProj, 256, SMB>>>(ffh, ffl, t_w2, u_w2, ffn_b2, bo, nullptr, nullptr, M_ROWS, C_DIM, DFF_DIM, 0, 1.f);
    add_ln_kernel<<<M_ROWS, 256>>>(by2, bo, ln3_g, ln3_b, (float*)d_out, nullptr, nullptr);
}

// round 16
// speedup vs baseline: 1.0240x; 1.0006x over previous
#include <cuda_runtime.h>
#include <cuda_bf16.h>
#include <math.h>
#include <stdint.h>

typedef __nv_bfloat16 bf16;

#define C_DIM   1024
#define T_DIM   1024
#define B_DIM   4
#define H_DIM   16
#define DK      64
#define DFF_DIM 4096
#define M_ROWS  4096

// Q pre-scale: 1/sqrt(dk) * log2(e)  (softmax via exp2)
#define QSCALE 0.1803368801111244f

// ---------------- scratch (device globals; no allocation allowed) ----------
__device__ float g_o [M_ROWS * C_DIM];
__device__ float g_y [M_ROWS * C_DIM];
__device__ float g_y2[M_ROWS * C_DIM];

__device__ bf16 g_qh [M_ROWS * C_DIM], g_ql [M_ROWS * C_DIM];
__device__ bf16 g_kh [M_ROWS * C_DIM], g_kl [M_ROWS * C_DIM];
__device__ bf16 g_vh [M_ROWS * C_DIM], g_vl [M_ROWS * C_DIM];
__device__ bf16 g_dsth[M_ROWS * C_DIM], g_dstl[M_ROWS * C_DIM];
__device__ bf16 g_srch[M_ROWS * C_DIM], g_srcl[M_ROWS * C_DIM];
__device__ bf16 g_yh  [M_ROWS * C_DIM], g_yl  [M_ROWS * C_DIM];
__device__ bf16 g_y2h [M_ROWS * C_DIM], g_y2l [M_ROWS * C_DIM];
__device__ bf16 g_ath [M_ROWS * C_DIM], g_atl [M_ROWS * C_DIM];
__device__ bf16 g_ffh [M_ROWS * DFF_DIM], g_ffl[M_ROWS * DFF_DIM];
__device__ bf16 g_wth [16 * 1024 * 1024], g_wtl[16 * 1024 * 1024];

// ---------------- PTX helpers (plain sm_103: no tcgen05/TMEM) --------------
__device__ __forceinline__ uint32_t smem_u32(const void* p) {
    uint32_t a;
    asm("{ .reg .u64 t; cvta.to.shared.u64 t, %1; cvt.u32.u64 %0, t; }" : "=r"(a) : "l"(p));
    return a;
}
#define SMEM_SWIZZLE_128B(o) ((o) ^ (((o) >> 3) & 0x70))

#define CP16(dst, src) \
    asm volatile("cp.async.cg.shared.global [%0], [%1], 16;" :: "r"(dst), "l"(src) : "memory")
#define CP_COMMIT() asm volatile("cp.async.commit_group;" ::: "memory")
#define CP_WAIT(n)  asm volatile("cp.async.wait_group %0;" :: "n"(n) : "memory")

#define LDSM4(r0, r1, r2, r3, a) \
    asm volatile("ldmatrix.sync.aligned.m8n8.x4.shared.b16 {%0,%1,%2,%3}, [%4];" \
                 : "=r"(r0), "=r"(r1), "=r"(r2), "=r"(r3) : "r"(a))
#define LDSM4T(r0, r1, r2, r3, a) \
    asm volatile("ldmatrix.sync.aligned.m8n8.x4.trans.shared.b16 {%0,%1,%2,%3}, [%4];" \
                 : "=r"(r0), "=r"(r1), "=r"(r2), "=r"(r3) : "r"(a))

#define MMA16816(d, a, b0, b1) \
    asm volatile("mma.sync.aligned.m16n8k16.row.col.f32.bf16.bf16.f32 " \
                 "{%0,%1,%2,%3}, {%4,%5,%6,%7}, {%8,%9}, {%0,%1,%2,%3};" \
                 : "+f"((d)[0]), "+f"((d)[1]), "+f"((d)[2]), "+f"((d)[3]) \
                 : "r"((a)[0]), "r"((a)[1]), "r"((a)[2]), "r"((a)[3]), "r"(b0), "r"(b1))

__device__ __forceinline__ void split2(float v, bf16& h, bf16& l) {
    h = __float2bfloat16(v);
    l = __float2bfloat16(v - __bfloat162float(h));
}
__device__ __forceinline__ void split_pack(float x, float y, uint32_t& hp, uint32_t& lp) {
    bf16 hx, lx, hy, ly;
    split2(x, hx, lx);
    split2(y, hy, ly);
    __nv_bfloat162 h2(hx, hy), l2(lx, ly);
    hp = *(uint32_t*)&h2;
    lp = *(uint32_t*)&l2;
}

// ---------------- HMMA GEMM (R8/R13-frozen): CTA 128x128, BK=32, 8 warps ---
#define GSTAGE 32768

__global__ __launch_bounds__(256, 2) void gemm_hmma(
    const bf16* __restrict__ Ah, const bf16* __restrict__ Al,
    const bf16* __restrict__ Bh, const bf16* __restrict__ Bl,
    const float* __restrict__ bias,
    float* __restrict__ outF, bf16* __restrict__ outH, bf16* __restrict__ outL,
    int M, int N, int K, int do_gelu, float oscale)
{
    extern __shared__ char dynsm[];
    const uint32_t sb0 = (smem_u32(dynsm) + 1023) & ~1023u;

    const int tid = threadIdx.x;
    const int m0 = blockIdx.y * 128;
    const int n0 = blockIdx.x * 128;
    const int w = tid >> 5, lane = tid & 31;
    const int wm0 = (w >> 2) * 64;
    const int wn0 = (w & 3) * 32;

    const int lr = tid >> 1;
    const int lc = (tid & 1) * 2;

    const int arow = lane & 15;
    const int ahalf = lane >> 4;
    const int brow = ((lane >> 4) & 1) * 8 + (lane & 7);
    const int bhalf = (lane >> 3) & 1;

    float acc[4][4][4];
#pragma unroll
    for (int i = 0; i < 4; i++)
#pragma unroll
        for (int j = 0; j < 4; j++)
#pragma unroll
            for (int r = 0; r < 4; r++) acc[i][j][r] = 0.f;

    const int NC = K >> 5;

    auto load_stage = [&](uint32_t sb, int k0) {
        const bf16* pa_h = Ah + (size_t)(m0 + lr) * K + k0 + lc * 8;
        const bf16* pa_l = Al + (size_t)(m0 + lr) * K + k0 + lc * 8;
        const bf16* pb_h = Bh + (size_t)(n0 + lr) * K + k0 + lc * 8;
        const bf16* pb_l = Bl + (size_t)(n0 + lr) * K + k0 + lc * 8;
        const uint32_t sw = (uint32_t)((lr >> 1) & 3);
#pragma unroll
        for (int j = 0; j < 2; j++) {
            const uint32_t off = (uint32_t)(lr * 64) + ((((uint32_t)(lc + j)) ^ sw) << 4);
            CP16(sb + off,         pa_h + j * 8);
            CP16(sb + 8192  + off, pa_l + j * 8);
            CP16(sb + 16384 + off, pb_h + j * 8);
            CP16(sb + 24576 + off, pb_l + j * 8);
        }
    };

    load_stage(sb0, 0);
    CP_COMMIT();

    for (int c = 0; c < NC; c++) {
        if (c + 1 < NC) {
            load_stage(sb0 + ((c + 1) & 1) * GSTAGE, (c + 1) * 32);
            CP_COMMIT();
            CP_WAIT(1);
        } else {
            CP_WAIT(0);
        }
        __syncthreads();

        const uint32_t sb = sb0 + (c & 1) * GSTAGE;
        const uint32_t sAh = sb, sAl = sb + 8192, sBh = sb + 16384, sBl = sb + 24576;

#pragma unroll
        for (int ks = 0; ks < 2; ks++) {
            uint32_t ah[4][4], al[4][4];
#pragma unroll
            for (int mt = 0; mt < 4; mt++) {
                const int row = wm0 + mt * 16 + arow;
                const uint32_t chunk = (uint32_t)(ks * 2 + ahalf);
                const uint32_t ad = (uint32_t)(row * 64) +
                                    ((chunk ^ ((uint32_t)(row >> 1) & 3)) << 4);
                LDSM4(ah[mt][0], ah[mt][1], ah[mt][2], ah[mt][3], sAh + ad);
                LDSM4(al[mt][0], al[mt][1], al[mt][2], al[mt][3], sAl + ad);
            }
            uint32_t fb[4][2];
            uint32_t bd0, bd1;
            {
                const int r0 = wn0 + brow, r1 = wn0 + 16 + brow;
                const uint32_t chunk = (uint32_t)(ks * 2 + bhalf);
                bd0 = (uint32_t)(r0 * 64) + ((chunk ^ ((uint32_t)(r0 >> 1) & 3)) << 4);
                bd1 = (uint32_t)(r1 * 64) + ((chunk ^ ((uint32_t)(r1 >> 1) & 3)) << 4);
            }
            LDSM4(fb[0][0], fb[0][1], fb[1][0], fb[1][1], sBh + bd0);
            LDSM4(fb[2][0], fb[2][1], fb[3][0], fb[3][1], sBh + bd1);
#pragma unroll
            for (int mt = 0; mt < 4; mt++)
#pragma unroll
                for (int nt = 0; nt < 4; nt++) {
                    MMA16816(acc[mt][nt], ah[mt], fb[nt][0], fb[nt][1]);
                    MMA16816(acc[mt][nt], al[mt], fb[nt][0], fb[nt][1]);
                }
            LDSM4(fb[0][0], fb[0][1], fb[1][0], fb[1][1], sBl + bd0);
            LDSM4(fb[2][0], fb[2][1], fb[3][0], fb[3][1], sBl + bd1);
#pragma unroll
            for (int mt = 0; mt < 4; mt++)
#pragma unroll
                for (int nt = 0; nt < 4; nt++)
                    MMA16816(acc[mt][nt], ah[mt], fb[nt][0], fb[nt][1]);
        }
        __syncthreads();
    }

    const int g = lane >> 2, q = lane & 3;
#pragma unroll
    for (int mt = 0; mt < 4; mt++) {
#pragma unroll
        for (int half = 0; half < 2; half++) {
            const int row = m0 + wm0 + mt * 16 + half * 8 + g;
#pragma unroll
            for (int nt = 0; nt < 4; nt++) {
                const int col = n0 + wn0 + nt * 8 + q * 2;
                float v0 = acc[mt][nt][half * 2 + 0] + __ldg(bias + col);
                float v1 = acc[mt][nt][half * 2 + 1] + __ldg(bias + col + 1);
                if (do_gelu) {
                    v0 = 0.5f * v0 * (1.f + erff(v0 * 0.70710678118654752f));
                    v1 = 0.5f * v1 * (1.f + erff(v1 * 0.70710678118654752f));
                }
                const size_t idx = (size_t)row * N + col;
                if (outF) *(float2*)(outF + idx) = make_float2(v0, v1);
                if (outH) {
                    uint32_t hp, lp;
                    split_pack(v0 * oscale, v1 * oscale, hp, lp);
                    *(uint32_t*)(outH + idx) = hp;
                    *(uint32_t*)(outL + idx) = lp;
                }
            }
        }
    }
}

// ---------------- HMMA flash attention (R15-frozen): 128 thr, occ-2 --------
__global__ __launch_bounds__(128, 2) void attention_hmma(
    const bf16* __restrict__ Qh, const bf16* __restrict__ Ql,
    const bf16* __restrict__ Kh, const bf16* __restrict__ Kl,
    const bf16* __restrict__ Vh, const bf16* __restrict__ Vl,
    bf16* __restrict__ OH, bf16* __restrict__ OL,
    int causal)
{
    extern __shared__ char dynsm[];
    const uint32_t sQ  = (smem_u32(dynsm) + 1023) & ~1023u;   // Qh 8K | Ql 8K
    const uint32_t sKV = sQ + 16384;                          // 2 stages x 32K

    const int tid = threadIdx.x;
    const int w = tid >> 5, lane = tid & 31;
    const int b = blockIdx.z, h = blockIdx.y;
    const int q0 = blockIdx.x * 64;
    const int wm0 = w * 16;
    const int g = lane >> 2, qd = lane & 3;

    {
        const int r = tid >> 1, c0 = (tid & 1) * 4;
        const size_t qrow = (size_t)(b * T_DIM + q0 + r) * C_DIM + h * DK;
#pragma unroll
        for (int c = c0; c < c0 + 4; c++) {
            const uint32_t off = SMEM_SWIZZLE_128B((uint32_t)(r * 128 + c * 16));
            CP16(sQ + off,        Qh + qrow + c * 8);
            CP16(sQ + 8192 + off, Ql + qrow + c * 8);
        }
    }
    auto load_kv = [&](uint32_t sb, int k0) {
        const int r = tid >> 1, c0 = (tid & 1) * 4;
        const size_t krow = (size_t)(b * T_DIM + k0 + r) * C_DIM + h * DK;
#pragma unroll
        for (int c = c0; c < c0 + 4; c++) {
            const uint32_t off = SMEM_SWIZZLE_128B((uint32_t)(r * 128 + c * 16));
            CP16(sb + off,         Kh + krow + c * 8);
            CP16(sb + 8192  + off, Kl + krow + c * 8);
            CP16(sb + 16384 + off, Vh + krow + c * 8);
            CP16(sb + 24576 + off, Vl + krow + c * 8);
        }
    };
    load_kv(sKV, 0);
    CP_COMMIT();

    const int ntiles = causal ? (q0 + 64) / 64 : (T_DIM / 64);

    float m0 = -1e30f, m1 = -1e30f, l0 = 0.f, l1 = 0.f;
    float o[8][4];
#pragma unroll
    for (int i = 0; i < 8; i++)
#pragma unroll
        for (int j = 0; j < 4; j++) o[i][j] = 0.f;

    uint32_t fqh[4][4], fql[4][4];
    const int arow = lane & 15, ahalf = lane >> 4;
    const int brow = ((lane >> 4) & 1) * 8 + (lane & 7), bhalf = (lane >> 3) & 1;
    const int vkrow = ((lane >> 3) & 1) * 8 + (lane & 7);
    const int vdsel = lane >> 4;

    for (int it = 0; it < ntiles; it++) {
        if (it + 1 < ntiles) {
            load_kv(sKV + ((it + 1) & 1) * 32768, (it + 1) * 64);
            CP_COMMIT();
            CP_WAIT(1);
        } else {
            CP_WAIT(0);
        }
        __syncthreads();

        if (it == 0) {
#pragma unroll
            for (int ks = 0; ks < 4; ks++) {
                const int row = wm0 + arow;
                const uint32_t ad = (uint32_t)(row * 128) +
                    (((uint32_t)(ks * 32 + ahalf * 16)) ^ ((uint32_t)(row & 7) << 4));
                LDSM4(fqh[ks][0], fqh[ks][1], fqh[ks][2], fqh[ks][3], sQ + ad);
                LDSM4(fql[ks][0], fql[ks][1], fql[ks][2], fql[ks][3], sQ + 8192 + ad);
            }
        }

        const uint32_t sb = sKV + (it & 1) * 32768;

        float s[8][4];
#pragma unroll
        for (int i = 0; i < 8; i++)
#pragma unroll
            for (int j = 0; j < 4; j++) s[i][j] = 0.f;

        uint32_t fb[8][2];
#pragma unroll
        for (int ks = 0; ks < 4; ks++) {
#pragma unroll
            for (int ng = 0; ng < 4; ng++) {
                const int row = ng * 16 + brow;
                const uint32_t bd = (uint32_t)(row * 128) +
                    (((uint32_t)(ks * 32 + bhalf * 16)) ^ ((uint32_t)(row & 7) << 4));
                LDSM4(fb[2*ng][0], fb[2*ng][1], fb[2*ng+1][0], fb[2*ng+1][1], sb + bd);
            }
#pragma unroll
            for (int nt = 0; nt < 8; nt++) {
                MMA16816(s[nt], fqh[ks], fb[nt][0], fb[nt][1]);
                MMA16816(s[nt], fql[ks], fb[nt][0], fb[nt][1]);
            }
#pragma unroll
            for (int ng = 0; ng < 4; ng++) {
                const int row = ng * 16 + brow;
                const uint32_t bd = (uint32_t)(row * 128) +
                    (((uint32_t)(ks * 32 + bhalf * 16)) ^ ((uint32_t)(row & 7) << 4));
                LDSM4(fb[2*ng][0], fb[2*ng][1], fb[2*ng+1][0], fb[2*ng+1][1], sb + 8192 + bd);
            }
#pragma unroll
            for (int nt = 0; nt < 8; nt++)
                MMA16816(s[nt], fqh[ks], fb[nt][0], fb[nt][1]);
        }

        const int kbase = it * 64;
        const int row0 = q0 + wm0 + g, row1 = row0 + 8;
        if (causal && kbase + 63 > row0) {
#pragma unroll
            for (int nt = 0; nt < 8; nt++) {
                const int cb = kbase + nt * 8 + qd * 2;
                if (cb     > row0) s[nt][0] = -1e30f;
                if (cb + 1 > row0) s[nt][1] = -1e30f;
                if (cb     > row1) s[nt][2] = -1e30f;
                if (cb + 1 > row1) s[nt][3] = -1e30f;
            }
        }

        float mx0 = -1e30f, mx1 = -1e30f;
#pragma unroll
        for (int nt = 0; nt < 8; nt++) {
            mx0 = fmaxf(mx0, fmaxf(s[nt][0], s[nt][1]));
            mx1 = fmaxf(mx1, fmaxf(s[nt][2], s[nt][3]));
        }
        mx0 = fmaxf(mx0, __shfl_xor_sync(0xffffffffu, mx0, 1));
        mx0 = fmaxf(mx0, __shfl_xor_sync(0xffffffffu, mx0, 2));
        mx1 = fmaxf(mx1, __shfl_xor_sync(0xffffffffu, mx1, 1));
        mx1 = fmaxf(mx1, __shfl_xor_sync(0xffffffffu, mx1, 2));

        const float mn0 = fmaxf(m0, mx0), mn1 = fmaxf(m1, mx1);
        const float a0 = exp2f(m0 - mn0), a1 = exp2f(m1 - mn1);
        m0 = mn0; m1 = mn1;
        l0 *= a0; l1 *= a1;
#pragma unroll
        for (int dt = 0; dt < 8; dt++) {
            o[dt][0] *= a0; o[dt][1] *= a0;
            o[dt][2] *= a1; o[dt][3] *= a1;
        }

        uint32_t phx[8][2], plx[8][2];
#pragma unroll
        for (int nt = 0; nt < 8; nt++) {
            const float p0 = exp2f(s[nt][0] - mn0), p1 = exp2f(s[nt][1] - mn0);
            const float p2 = exp2f(s[nt][2] - mn1), p3 = exp2f(s[nt][3] - mn1);
            l0 += p0 + p1; l1 += p2 + p3;
            split_pack(p0, p1, phx[nt][0], plx[nt][0]);
            split_pack(p2, p3, phx[nt][1], plx[nt][1]);
        }

#pragma unroll
        for (int ks = 0; ks < 4; ks++) {
            uint32_t pa_h[4] = {phx[2*ks][0], phx[2*ks][1], phx[2*ks+1][0], phx[2*ks+1][1]};
            uint32_t pa_l[4] = {plx[2*ks][0], plx[2*ks][1], plx[2*ks+1][0], plx[2*ks+1][1]};
#pragma unroll
            for (int p = 0; p < 4; p++) {
                const int row = ks * 16 + vkrow;
                const uint32_t bd = (uint32_t)(row * 128) +
                    (((uint32_t)((p * 2 + vdsel) * 16)) ^ ((uint32_t)(row & 7) << 4));
                LDSM4T(fb[2*p][0], fb[2*p][1], fb[2*p+1][0], fb[2*p+1][1], sb + 16384 + bd);
            }
#pragma unroll
            for (int dt = 0; dt < 8; dt++) {
                MMA16816(o[dt], pa_h, fb[dt][0], fb[dt][1]);
                MMA16816(o[dt], pa_l, fb[dt][0], fb[dt][1]);
            }
#pragma unroll
            for (int p = 0; p < 4; p++) {
                const int row = ks * 16 + vkrow;
                const uint32_t bd = (uint32_t)(row * 128) +
                    (((uint32_t)((p * 2 + vdsel) * 16)) ^ ((uint32_t)(row & 7) << 4));
                LDSM4T(fb[2*p][0], fb[2*p][1], fb[2*p+1][0], fb[2*p+1][1], sb + 24576 + bd);
            }
#pragma unroll
            for (int dt = 0; dt < 8; dt++)
                MMA16816(o[dt], pa_h, fb[dt][0], fb[dt][1]);
        }
        __syncthreads();
    }

    l0 += __shfl_xor_sync(0xffffffffu, l0, 1);
    l0 += __shfl_xor_sync(0xffffffffu, l0, 2);
    l1 += __shfl_xor_sync(0xffffffffu, l1, 1);
    l1 += __shfl_xor_sync(0xffffffffu, l1, 2);
    const float i0 = 1.f / l0, i1 = 1.f / l1;

    const size_t or0 = (size_t)(b * T_DIM + q0 + wm0 + g) * C_DIM + h * DK;
    const size_t or1 = or0 + 8 * (size_t)C_DIM;
#pragma unroll
    for (int dt = 0; dt < 8; dt++) {
        const int col = dt * 8 + qd * 2;
        uint32_t hp, lp;
        split_pack(o[dt][0] * i0, o[dt][1] * i0, hp, lp);
        *(uint32_t*)(OH + or0 + col) = hp;
        *(uint32_t*)(OL + or0 + col) = lp;
        split_pack(o[dt][2] * i1, o[dt][3] * i1, hp, lp);
        *(uint32_t*)(OH + or1 + col) = hp;
        *(uint32_t*)(OL + or1 + col) = lp;
    }
}

// ---------------- unified batched transpose+split: 16 x [1024x1024] slices --
// Each slice z: transpose a 1024x1024 block from W (input row stride inS)
// into Th/Tl (output row stride outS). FFN weights are expressed as strided
// slices of their parent matrices.
struct TW16 {
    const float* w[16];
    bf16* th[16];
    bf16* tl[16];
    int inS[16];
    int outS[16];
};

__global__ __launch_bounds__(256) void transpose_split16(TW16 tw)
{
    __shared__ float tile[32][33];
    const int z = blockIdx.z;
    const float* __restrict__ W = tw.w[z];
    bf16* __restrict__ Th = tw.th[z];
    bf16* __restrict__ Tl = tw.tl[z];
    const int inS = tw.inS[z], outS = tw.outS[z];
    const int tx = threadIdx.x, ty = threadIdx.y;
    const int n = blockIdx.x * 32 + tx;
    const int k = blockIdx.y * 32 + ty;
#pragma unroll
    for (int j = 0; j < 4; j++)
        tile[ty + j * 8][tx] = W[(size_t)(k + j * 8) * inS + n];
    __syncthreads();
    const int n2 = blockIdx.x * 32 + ty;
    const int k2 = blockIdx.y * 32 + tx;
#pragma unroll
    for (int j = 0; j < 4; j++) {
        float v = tile[tx][ty + j * 8];
        bf16 h, l;
        split2(v, h, l);
        Th[(size_t)(n2 + j * 8) * outS + k2] = h;
        Tl[(size_t)(n2 + j * 8) * outS + k2] = l;
    }
}

// ---------------- batched elementwise split (dst + src) ---------------------
__global__ __launch_bounds__(256) void split2_kernel(
    const float* __restrict__ x0, bf16* __restrict__ h0, bf16* __restrict__ l0v,
    const float* __restrict__ x1, bf16* __restrict__ h1, bf16* __restrict__ l1v)
{
    const float* x = blockIdx.y ? x1 : x0;
    bf16* hh = blockIdx.y ? h1 : h0;
    bf16* ll = blockIdx.y ? l1v : l0v;
    const int i = (blockIdx.x * 256 + threadIdx.x) * 4;
    float4 v = *(const float4*)(x + i);
    uint32_t hp, lp;
    split_pack(v.x, v.y, hp, lp);
    *(uint32_t*)(hh + i) = hp;
    *(uint32_t*)(ll + i) = lp;
    split_pack(v.z, v.w, hp, lp);
    *(uint32_t*)(hh + i + 2) = hp;
    *(uint32_t*)(ll + i + 2) = lp;
}

// ---------------- fused residual add + LayerNorm (+ optional bf16 split) ----
__global__ __launch_bounds__(256) void add_ln_kernel(
    const float* __restrict__ res, const float* __restrict__ dlt,
    const float* __restrict__ gg, const float* __restrict__ bb,
    float* __restrict__ out, bf16* __restrict__ oh, bf16* __restrict__ ol)
{
    __shared__ float sh_s[8], sh_q[8];
    const int row = blockIdx.x;
    const int tid = threadIdx.x;

    const float4 rv = *(const float4*)(res + (size_t)row * C_DIM + tid * 4);
    const float4 dv = *(const float4*)(dlt + (size_t)row * C_DIM + tid * 4);
    const float x0 = rv.x + dv.x, x1 = rv.y + dv.y;
    const float x2 = rv.z + dv.z, x3 = rv.w + dv.w;

    float s  = x0 + x1 + x2 + x3;
    float ss = x0*x0 + x1*x1 + x2*x2 + x3*x3;
#pragma unroll
    for (int off = 16; off > 0; off >>= 1) {
        s  += __shfl_xor_sync(0xffffffffu, s,  off);
        ss += __shfl_xor_sync(0xffffffffu, ss, off);
    }
    if ((tid & 31) == 0) { sh_s[tid >> 5] = s; sh_q[tid >> 5] = ss; }
    __syncthreads();
    s = 0.f; ss = 0.f;
#pragma unroll
    for (int w = 0; w < 8; w++) { s += sh_s[w]; ss += sh_q[w]; }

    const float mu   = s * (1.f / (float)C_DIM);
    const float var  = ss * (1.f / (float)C_DIM) - mu * mu;
    const float rstd = rsqrtf(var + 1e-12f);

    const float4 gv = *(const float4*)(gg + tid * 4);
    const float4 bv = *(const float4*)(bb + tid * 4);
    float4 ov;
    ov.x = (x0 - mu) * rstd * gv.x + bv.x;
    ov.y = (x1 - mu) * rstd * gv.y + bv.y;
    ov.z = (x2 - mu) * rstd * gv.z + bv.z;
    ov.w = (x3 - mu) * rstd * gv.w + bv.w;
    *(float4*)(out + (size_t)row * C_DIM + tid * 4) = ov;

    if (oh) {
        const size_t ib = (size_t)row * C_DIM + tid * 4;
        uint32_t hp, lp;
        split_pack(ov.x, ov.y, hp, lp);
        *(uint32_t*)(oh + ib) = hp;
        *(uint32_t*)(ol + ib) = lp;
        split_pack(ov.z, ov.w, hp, lp);
        *(uint32_t*)(oh + ib + 2) = hp;
        *(uint32_t*)(ol + ib + 2) = lp;
    }
}

// ---------------- launch ----------------------------------------------------
extern "C" void kernel_launch(void* const* d_in, const int* in_sizes, int n_in,
                              void* d_out, int out_size)
{
    const float* src = (const float*)d_in[0];
    const float* dst = (const float*)d_in[1];
    const float* sa_wq = (const float*)d_in[4];
    const float* sa_wk = (const float*)d_in[5];
    const float* sa_wv = (const float*)d_in[6];
    const float* sa_wo = (const float*)d_in[7];
    const float* sa_bq = (const float*)d_in[8];
    const float* sa_bk = (const float*)d_in[9];
    const float* sa_bv = (const float*)d_in[10];
    const float* sa_bo = (const float*)d_in[11];
    const float* ca_wq = (const float*)d_in[12];
    const float* ca_wk = (const float*)d_in[13];
    const float* ca_wv = (const float*)d_in[14];
    const float* ca_wo = (const float*)d_in[15];
    const float* ca_bq = (const float*)d_in[16];
    const float* ca_bk = (const float*)d_in[17];
    const float* ca_bv = (const float*)d_in[18];
    const float* ca_bo = (const float*)d_in[19];
    const float* ffn_w1 = (const float*)d_in[20];
    const float* ffn_b1 = (const float*)d_in[21];
    const float* ffn_w2 = (const float*)d_in[22];
    const float* ffn_b2 = (const float*)d_in[23];
    const float* ln1_g = (const float*)d_in[24];
    const float* ln1_b = (const float*)d_in[25];
    const float* ln2_g = (const float*)d_in[26];
    const float* ln2_b = (const float*)d_in[27];
    const float* ln3_g = (const float*)d_in[28];
    const float* ln3_b = (const float*)d_in[29];

    float *bo, *by, *by2;
    bf16 *qh, *ql, *kh, *kl, *vh, *vl;
    bf16 *dsth, *dstl, *srch, *srcl, *yh, *yl, *y2h, *y2l, *ath, *atl, *ffh, *ffl, *wth, *wtl;
    cudaGetSymbolAddress((void**)&bo,  g_o);
    cudaGetSymbolAddress((void**)&by,  g_y);
    cudaGetSymbolAddress((void**)&by2, g_y2);
    cudaGetSymbolAddress((void**)&qh,  g_qh);
    cudaGetSymbolAddress((void**)&ql,  g_ql);
    cudaGetSymbolAddress((void**)&kh,  g_kh);
    cudaGetSymbolAddress((void**)&kl,  g_kl);
    cudaGetSymbolAddress((void**)&vh,  g_vh);
    cudaGetSymbolAddress((void**)&vl,  g_vl);
    cudaGetSymbolAddress((void**)&dsth, g_dsth);
    cudaGetSymbolAddress((void**)&dstl, g_dstl);
    cudaGetSymbolAddress((void**)&srch, g_srch);
    cudaGetSymbolAddress((void**)&srcl, g_srcl);
    cudaGetSymbolAddress((void**)&yh,  g_yh);
    cudaGetSymbolAddress((void**)&yl,  g_yl);
    cudaGetSymbolAddress((void**)&y2h, g_y2h);
    cudaGetSymbolAddress((void**)&y2l, g_y2l);
    cudaGetSymbolAddress((void**)&ath, g_ath);
    cudaGetSymbolAddress((void**)&atl, g_atl);
    cudaGetSymbolAddress((void**)&ffh, g_ffh);
    cudaGetSymbolAddress((void**)&ffl, g_ffl);
    cudaGetSymbolAddress((void**)&wth, g_wth);
    cudaGetSymbolAddress((void**)&wtl, g_wtl);

    const size_t SMB = 2 * GSTAGE + 1024;        // GEMM: 65 KB (2 CTAs/SM)
    const size_t SMA = 16384 + 2 * 32768 + 1024; // attention: 81 KB (2 CTAs/SM)
    cudaFuncSetAttribute(gemm_hmma, cudaFuncAttributeMaxDynamicSharedMemorySize, (int)SMB);
    cudaFuncSetAttribute(attention_hmma, cudaFuncAttributeMaxDynamicSharedMemorySize, (int)SMA);

    const size_t OW = 1024 * 1024;
    bf16 *t_sa_wq = wth + 0*OW, *t_sa_wk = wth + 1*OW, *t_sa_wv = wth + 2*OW, *t_sa_wo = wth + 3*OW;
    bf16 *t_ca_wq = wth + 4*OW, *t_ca_wk = wth + 5*OW, *t_ca_wv = wth + 6*OW, *t_ca_wo = wth + 7*OW;
    bf16 *t_w1 = wth + 8*OW, *t_w2 = wth + 12*OW;
    bf16 *u_sa_wq = wtl + 0*OW, *u_sa_wk = wtl + 1*OW, *u_sa_wv = wtl + 2*OW, *u_sa_wo = wtl + 3*OW;
    bf16 *u_ca_wq = wtl + 4*OW, *u_ca_wk = wtl + 5*OW, *u_ca_wv = wtl + 6*OW, *u_ca_wo = wtl + 7*OW;
    bf16 *u_w1 = wtl + 8*OW, *u_w2 = wtl + 12*OW;

    // ---- all weight transposes in ONE launch (16 strided 1024x1024 slices) --
    TW16 tw;
    const float* sqw[8] = {sa_wq, sa_wk, sa_wv, sa_wo, ca_wq, ca_wk, ca_wv, ca_wo};
    bf16* sqt[8] = {t_sa_wq, t_sa_wk, t_sa_wv, t_sa_wo, t_ca_wq, t_ca_wk, t_ca_wv, t_ca_wo};
    bf16* squ[8] = {u_sa_wq, u_sa_wk, u_sa_wv, u_sa_wo, u_ca_wq, u_ca_wk, u_ca_wv, u_ca_wo};
    for (int z = 0; z < 8; z++) {
        tw.w[z] = sqw[z]; tw.th[z] = sqt[z]; tw.tl[z] = squ[z];
        tw.inS[z] = 1024; tw.outS[z] = 1024;
    }
    // ffn_w1 [1024,4096] -> t_w1 [4096,1024]: column-block z' of input is a
    // strided 1024x1024 transpose into output row-block z'.
    for (int z = 0; z < 4; z++) {
        tw.w[8 + z]  = ffn_w1 + z * 1024;        // column offset, row stride 4096
        tw.th[8 + z] = t_w1 + (size_t)z * OW;    // output row block, stride 1024
        tw.tl[8 + z] = u_w1 + (size_t)z * OW;
        tw.inS[8 + z] = 4096; tw.outS[8 + z] = 1024;
    }
    // ffn_w2 [4096,1024] -> t_w2 [1024,4096]: input row-block z' transposes
    // into output column-block z' (output row stride 4096).
    for (int z = 0; z < 4; z++) {
        tw.w[12 + z]  = ffn_w2 + (size_t)z * OW; // input row block, stride 1024
        tw.th[12 + z] = t_w2 + z * 1024;         // output column offset, stride 4096
        tw.tl[12 + z] = u_w2 + z * 1024;
        tw.inS[12 + z] = 1024; tw.outS[12 + z] = 4096;
    }

    const dim3 tb(32, 8);
    transpose_split16<<<dim3(32, 32, 16), tb>>>(tw);

    split2_kernel<<<dim3(4096, 2), 256>>>(dst, dsth, dstl, src, srch, srcl);

    const dim3 gProj(C_DIM / 128, M_ROWS / 128);     // (8, 32)  = 256 CTAs
    const dim3 gFfn1(DFF_DIM / 128, M_ROWS / 128);   // (32, 32) = 1024 CTAs
    const dim3 gAttn(T_DIM / 64, H_DIM, B_DIM);      // (16, 16, 4) = 1024 CTAs

    // ---- self attention (causal) ----
    gemm_hmma<<<gProj, 256, SMB>>>(dsth, dstl, t_sa_wq, u_sa_wq, sa_bq, nullptr, qh, ql, M_ROWS, C_DIM, C_DIM, 0, QSCALE);
    gemm_hmma<<<gProj, 256, SMB>>>(dsth, dstl, t_sa_wk, u_sa_wk, sa_bk, nullptr, kh, kl, M_ROWS, C_DIM, C_DIM, 0, 1.f);
    gemm_hmma<<<gProj, 256, SMB>>>(dsth, dstl, t_sa_wv, u_sa_wv, sa_bv, nullptr, vh, vl, M_ROWS, C_DIM, C_DIM, 0, 1.f);
    attention_hmma<<<gAttn, 128, SMA>>>(qh, ql, kh, kl, vh, vl, ath, atl, 1);
    gemm_hmma<<<gProj, 256, SMB>>>(ath, atl, t_sa_wo, u_sa_wo, sa_bo, bo, nullptr, nullptr, M_ROWS, C_DIM, C_DIM, 0, 1.f);
    add_ln_kernel<<<M_ROWS, 256>>>(dst, bo, ln1_g, ln1_b, by, yh, yl);

    // ---- cross attention (no mask) ----
    gemm_hmma<<<gProj, 256, SMB>>>(yh, yl, t_ca_wq, u_ca_wq, ca_bq, nullptr, qh, ql, M_ROWS, C_DIM, C_DIM, 0, QSCALE);
    gemm_hmma<<<gProj, 256, SMB>>>(srch, srcl, t_ca_wk, u_ca_wk, ca_bk, nullptr, kh, kl, M_ROWS, C_DIM, C_DIM, 0, 1.f);
    gemm_hmma<<<gProj, 256, SMB>>>(srch, srcl, t_ca_wv, u_ca_wv, ca_bv, nullptr, vh, vl, M_ROWS, C_DIM, C_DIM, 0, 1.f);
    attention_hmma<<<gAttn, 128, SMA>>>(qh, ql, kh, kl, vh, vl, ath, atl, 0);
    gemm_hmma<<<gProj, 256, SMB>>>(ath, atl, t_ca_wo, u_ca_wo, ca_bo, bo, nullptr, nullptr, M_ROWS, C_DIM, C_DIM, 0, 1.f);
    add_ln_kernel<<<M_ROWS, 256>>>(by, bo, ln2_g, ln2_b, by2, y2h, y2l);

    // ---- FFN ----
    gemm_hmma<<<gFfn1, 256, SMB>>>(y2h, y2l, t_w1, u_w1, ffn_b1, nullptr, ffh, ffl, M_ROWS, DFF_DIM, C_DIM, 1, 1.f);
    gemm_hmma<<<gProj, 256, SMB>>>(ffh, ffl, t_w2, u_w2, ffn_b2, bo, nullptr, nullptr, M_ROWS, C_DIM, DFF_DIM, 0, 1.f);
    add_ln_kernel<<<M_ROWS, 256>>>(by2, bo, ln3_g, ln3_b, (float*)d_out, nullptr, nullptr);
}